// round 9
// baseline (speedup 1.0000x reference)
#include <cuda_runtime.h>
#include <cuda_bf16.h>
#include <cstdint>

typedef __nv_bfloat16 bf;

#define NB_   4
#define BATCH 8
#define LEN   4096
#define FREQ  80
#define DIM   512
#define HID   2048
#define USEQ  1024
#define C1    128
#define C2    256
#define C3    512
#define H1    2048
#define W1    40
#define H2    1024
#define W2    20
#define MCONV (BATCH*H2*W2)      /* 163840 */
#define K2C   (9*C1)             /* 1152 */
#define K3C   (9*C2)             /* 2304 */
#define KE    (C3*W2)            /* 10240 */
#define MT    (BATCH*USEQ)       /* 8192 */
#define HTOK  (MT*DIM)           /* 4194304 */

// ---------------- scratch (device globals; no allocations) ----------------
__device__ float g_conv1[BATCH*H1*W1*C1];
__device__ bf g_col2h[MCONV*K2C],  g_col2l[MCONV*K2C];
__device__ bf g_c2h[MCONV*C2],     g_c2l[MCONV*C2];
__device__ bf g_col3h[MCONV*K3C],  g_col3l[MCONV*K3C];
__device__ bf g_c3h[MCONV*C3],     g_c3l[MCONV*C3];
__device__ bf g_yrh[MT*KE],        g_yrl[MT*KE];
__device__ float g_t0[HTOK];
__device__ float g_h[HTOK];
__device__ float g_xn[HTOK];
__device__ bf g_xkh[HTOK], g_xkl[HTOK];
__device__ bf g_xvh[HTOK], g_xvl[HTOK];
__device__ bf g_xrh[HTOK], g_xrl[HTOK];
__device__ float g_k[HTOK];
__device__ float g_v[HTOK];
__device__ float g_r[HTOK];
__device__ bf g_rwh[HTOK], g_rwl[HTOK];
__device__ bf g_kkh[MT*HID], g_kkl[MT*HID];
// transposed+split weights, [N][K] K-major bf16 hi/lo
__device__ bf g_w2Th[C2*K2C],  g_w2Tl[C2*K2C];
__device__ bf g_w3Th[C3*K3C],  g_w3Tl[C3*K3C];
__device__ bf g_ewTh[DIM*KE],  g_ewTl[DIM*KE];
__device__ bf g_aqkvTh[NB_*3*DIM*DIM], g_aqkvTl[NB_*3*DIM*DIM];
__device__ bf g_awoTh[NB_*DIM*DIM],    g_awoTl[NB_*DIM*DIM];
__device__ bf g_fkrTh[NB_*(HID+DIM)*DIM], g_fkrTl[NB_*(HID+DIM)*DIM];
__device__ bf g_fwvTh[NB_*DIM*HID],    g_fwvTl[NB_*DIM*HID];

// ================== helpers ==================
__device__ __forceinline__ uint32_t smem_to_u32(const void* p) {
  uint32_t a;
  asm("{ .reg .u64 t; cvta.to.shared.u64 t, %1; cvt.u32.u64 %0, t; }"
      : "=r"(a) : "l"(p));
  return a;
}
__device__ __forceinline__ void ldsm4(uint32_t* r, uint32_t addr){
  asm volatile("ldmatrix.sync.aligned.m8n8.x4.shared.b16 {%0,%1,%2,%3}, [%4];"
    : "=r"(r[0]),"=r"(r[1]),"=r"(r[2]),"=r"(r[3]) : "r"(addr));
}
__device__ __forceinline__ void mma_bf16(float* d, const uint32_t* a, const uint32_t* b){
  asm volatile("mma.sync.aligned.m16n8k16.row.col.f32.bf16.bf16.f32 "
    "{%0,%1,%2,%3}, {%4,%5,%6,%7}, {%8,%9}, {%0,%1,%2,%3};"
    : "+f"(d[0]),"+f"(d[1]),"+f"(d[2]),"+f"(d[3])
    : "r"(a[0]),"r"(a[1]),"r"(a[2]),"r"(a[3]), "r"(b[0]),"r"(b[1]));
}
__device__ __forceinline__ void cp16(uint32_t s, const void* g){
  asm volatile("cp.async.cg.shared.global [%0], [%1], 16;" :: "r"(s), "l"(g));
}
#define CP_COMMIT() asm volatile("cp.async.commit_group;" ::: "memory")
#define CP_WAIT1()  asm volatile("cp.async.wait_group 1;" ::: "memory")

__device__ __forceinline__ void split2(float v0, float v1, uint32_t& h, uint32_t& l){
  __nv_bfloat162 hh = __floats2bfloat162_rn(v0, v1);
  float r0 = v0 - __bfloat162float(hh.x);
  float r1 = v1 - __bfloat162float(hh.y);
  __nv_bfloat162 ll = __floats2bfloat162_rn(r0, r1);
  h = *(uint32_t*)&hh; l = *(uint32_t*)&ll;
}
__device__ __forceinline__ void split4(float4 v, uint2& hi, uint2& lo){
  split2(v.x, v.y, hi.x, lo.x);
  split2(v.z, v.w, hi.y, lo.y);
}
__device__ __forceinline__ float sgm(float v){ return 1.f/(1.f + __expf(-v)); }

// ====== bf16x3 MMA GEMM: CTA 128x128, Kchunk=32, 16 warps (32x32 tiles) ======
// 3-stage cp.async pipeline. C = epi(act(A @ Wt^T + bias))
// ACT: 0 none,1 relu,2 sigmoid,3 relu^2 ; EPI: 0 store,1 +=,2 C+mul*acc
// OUT: 0 fp32 C ; 1 bf16 split Ch/Cl
#define PITCH 40
#define AHI_O 0
#define ALO_O 10240
#define BHI_O 20480
#define BLO_O 30720
#define STG_B 40960
#define MSMEM (3*STG_B)

template<int ACT, int EPI, int OUT>
__global__ void __launch_bounds__(512, 1) mgemm_k(int M, int N, int K,
    const bf* __restrict__ Ah, const bf* __restrict__ Al,
    const bf* __restrict__ Bh, const bf* __restrict__ Bl,
    const float* __restrict__ bias, float* __restrict__ C,
    bf* __restrict__ Ch, bf* __restrict__ Cl, const float* __restrict__ mul){
  extern __shared__ char smarr[];
  uint32_t smb = smem_to_u32(smarr);
  int tid = threadIdx.x, lane = tid & 31, wid = tid >> 5;
  int wm = wid >> 2, wn = wid & 3;          // warp grid 4(m) x 4(n)
  long m0 = (long)blockIdx.y * 128;
  int  n0 = blockIdx.x * 128;

  // loader: 4 arrays (Ah,Al,Bh,Bl) x 128 rows; each thread: one row of one array
  int larr = tid >> 7;                      // 0..3
  int lrow = tid & 127;
  const bf* lgp;
  uint32_t lao;
  if(larr == 0){ lgp = Ah + (m0 + lrow)*(long)K;        lao = AHI_O; }
  else if(larr == 1){ lgp = Al + (m0 + lrow)*(long)K;   lao = ALO_O; }
  else if(larr == 2){ lgp = Bh + ((long)n0 + lrow)*K;   lao = BHI_O; }
  else { lgp = Bl + ((long)n0 + lrow)*K;                lao = BLO_O; }
  uint32_t lso = lao + (uint32_t)lrow*80;

  // ldmatrix per-lane byte offsets (within hi arrays; lo at +ALO/BLO delta)
  uint32_t aoff = (((uint32_t)wm*32 + ((lane>>3)&1)*8 + (lane&7))*PITCH + ((lane>>4)&1)*8) * 2;
  uint32_t boff = (((uint32_t)wn*32 + ((lane>>4)&1)*8 + (lane&7))*PITCH + ((lane>>3)&1)*8) * 2;

  float acc[2][4][4];
  #pragma unroll
  for(int i=0;i<2;i++)
    #pragma unroll
    for(int j=0;j<4;j++)
      #pragma unroll
      for(int q=0;q<4;q++) acc[i][j][q] = 0.f;

  int nc = K >> 5;

  #define LOAD_CHUNK(c, sidx) do { \
    uint32_t stg_ = smb + (sidx)*STG_B + lso; \
    const bf* gp_ = lgp + (long)(c)*32; \
    cp16(stg_,      gp_); \
    cp16(stg_ + 16, gp_ + 8); \
    cp16(stg_ + 32, gp_ + 16); \
    cp16(stg_ + 48, gp_ + 24); \
  } while(0)

  LOAD_CHUNK(0, 0); CP_COMMIT();
  LOAD_CHUNK(1, 1); CP_COMMIT();

  for(int c = 0; c < nc; c++){
    CP_WAIT1();
    __syncthreads();
    if(c + 2 < nc){ LOAD_CHUNK(c + 2, (c + 2) % 3); }
    CP_COMMIT();
    uint32_t stg = smb + (c % 3)*STG_B;
    #pragma unroll
    for(int ks = 0; ks < 2; ks++){
      uint32_t ahk[2][4], alk[2][4], bhk[2][4], blk[2][4];
      #pragma unroll
      for(int mt = 0; mt < 2; mt++){
        uint32_t ad = stg + AHI_O + aoff + mt*(16*PITCH*2) + ks*32;
        ldsm4(ahk[mt], ad);
        ldsm4(alk[mt], ad + (ALO_O - AHI_O));
      }
      #pragma unroll
      for(int ng = 0; ng < 2; ng++){
        uint32_t bd = stg + BHI_O + boff + ng*(16*PITCH*2) + ks*32;
        ldsm4(bhk[ng], bd);
        ldsm4(blk[ng], bd + (BLO_O - BHI_O));
      }
      #pragma unroll
      for(int mt = 0; mt < 2; mt++)
        #pragma unroll
        for(int nt = 0; nt < 4; nt++)
          mma_bf16(acc[mt][nt], ahk[mt], &bhk[nt>>1][(nt&1)*2]);
      #pragma unroll
      for(int mt = 0; mt < 2; mt++)
        #pragma unroll
        for(int nt = 0; nt < 4; nt++)
          mma_bf16(acc[mt][nt], ahk[mt], &blk[nt>>1][(nt&1)*2]);
      #pragma unroll
      for(int mt = 0; mt < 2; mt++)
        #pragma unroll
        for(int nt = 0; nt < 4; nt++)
          mma_bf16(acc[mt][nt], alk[mt], &bhk[nt>>1][(nt&1)*2]);
    }
  }

  // ---- epilogue ----
  int mrow = lane >> 2;
  int ncol = (lane & 3) * 2;
  #pragma unroll
  for(int mt = 0; mt < 2; mt++){
    #pragma unroll
    for(int nt = 0; nt < 4; nt++){
      #pragma unroll
      for(int hf = 0; hf < 2; hf++){
        long gm = m0 + wm*32 + mt*16 + mrow + hf*8;
        int  gn = n0 + wn*32 + nt*8 + ncol;
        float v0 = acc[mt][nt][hf*2+0];
        float v1 = acc[mt][nt][hf*2+1];
        if(bias){ v0 += bias[gn]; v1 += bias[gn+1]; }
        if(ACT == 1){ v0 = fmaxf(v0,0.f); v1 = fmaxf(v1,0.f); }
        else if(ACT == 2){ v0 = sgm(v0); v1 = sgm(v1); }
        else if(ACT == 3){ v0 = fmaxf(v0,0.f); v0 *= v0; v1 = fmaxf(v1,0.f); v1 *= v1; }
        if(OUT == 0){
          float* cp = C + gm*N + gn;
          if(EPI == 1){ v0 += cp[0]; v1 += cp[1]; }
          else if(EPI == 2){
            const float* mp = mul + gm*N + gn;
            v0 = cp[0] + mp[0]*v0; v1 = cp[1] + mp[1]*v1;
          }
          *(float2*)cp = make_float2(v0, v1);
        } else {
          uint32_t hh, ll;
          split2(v0, v1, hh, ll);
          *(uint32_t*)&Ch[gm*N + gn] = hh;
          *(uint32_t*)&Cl[gm*N + gn] = ll;
        }
      }
    }
  }
}

// ---------------- conv1 ------------------------------------------------------
__global__ void conv1_k(const float* __restrict__ x, const float* __restrict__ w,
                        const float* __restrict__ bias){
  int t = blockIdx.x*256 + threadIdx.x;
  int co = t & 127;
  int rest = t >> 7;
  int wo = rest % W1; rest /= W1;
  int ho = rest % H1; int b = rest / H1;
  float acc = bias[co];
  int hi0 = 2*ho - 1, wi0 = 2*wo - 1;
  #pragma unroll
  for(int kh=0; kh<3; kh++){
    int hi = hi0 + kh;
    if(hi < 0 || hi >= LEN) continue;
    #pragma unroll
    for(int kw=0; kw<3; kw++){
      int wi = wi0 + kw;
      if(wi < 0 || wi >= FREQ) continue;
      acc = fmaf(x[(hi + (long)b*LEN)*FREQ + wi], w[co*9 + kh*3 + kw], acc);
    }
  }
  g_conv1[t] = fmaxf(acc, 0.f);
}

// ---------------- conv weight prep -------------------------------------------
__global__ void prep_conv_k(const float* __restrict__ w2, const float* __restrict__ w3){
  int t = blockIdx.x*256 + threadIdx.x;
  if(t < C2*K2C){
    int co = t / K2C; int idx = t % K2C;
    int r = idx / C1; int ci = idx % C1;
    float v = w2[co*(C1*9) + ci*9 + r];
    bf h = __float2bfloat16(v);
    g_w2Th[t] = h; g_w2Tl[t] = __float2bfloat16(v - __bfloat162float(h));
  } else {
    int u = t - C2*K2C;
    if(u >= C3*K3C) return;
    int co = u / K3C; int idx = u % K3C;
    int r = idx / C2; int ci = idx % C2;
    float v = w3[co*(C2*9) + ci*9 + r];
    bf h = __float2bfloat16(v);
    g_w3Th[u] = h; g_w3Tl[u] = __float2bfloat16(v - __bfloat162float(h));
  }
}

// ------ big weight prep: transpose [R][C]->[C][R] + split + concat -----------
__global__ void prep_big_k(const float* __restrict__ embed_w,
                           const float* __restrict__ awk, const float* __restrict__ awv,
                           const float* __restrict__ awr, const float* __restrict__ awo,
                           const float* __restrict__ fwr, const float* __restrict__ fwk,
                           const float* __restrict__ fwv){
  int t = blockIdx.x;
  const float* in; bf *oh, *ol; int R, C, tr, tc;
  if(t < 5120){
    in = embed_w; oh = g_ewTh; ol = g_ewTl; R = KE; C = DIM;
    tr = t / 16; tc = t % 16;
  } else {
    int u = t - 5120;
    int i = u / 3328; int v = u % 3328;
    long o2 = (long)i*DIM*DIM, oh2 = (long)i*DIM*HID;
    long qb = (long)i*3*DIM*DIM, fb = (long)i*(HID+DIM)*DIM;
    if(v < 768){
      int kind = v / 256; int vv = v % 256;
      R = DIM; C = DIM; tr = vv / 16; tc = vv % 16;
      in = (kind == 0 ? awk : kind == 1 ? awv : awr) + o2;
      oh = g_aqkvTh + qb + (long)kind*DIM*DIM;
      ol = g_aqkvTl + qb + (long)kind*DIM*DIM;
    } else if(v < 1024){
      int vv = v - 768;
      R = DIM; C = DIM; tr = vv / 16; tc = vv % 16;
      in = awo + o2; oh = g_awoTh + o2; ol = g_awoTl + o2;
    } else if(v < 2048){
      int vv = v - 1024;
      R = DIM; C = HID; tr = vv / 64; tc = vv % 64;
      in = fwk + oh2; oh = g_fkrTh + fb; ol = g_fkrTl + fb;
    } else if(v < 2304){
      int vv = v - 2048;
      R = DIM; C = DIM; tr = vv / 16; tc = vv % 16;
      in = fwr + o2;
      oh = g_fkrTh + fb + (long)HID*DIM;
      ol = g_fkrTl + fb + (long)HID*DIM;
    } else {
      int vv = v - 2304;
      R = HID; C = DIM; tr = vv / 16; tc = vv % 16;
      in = fwv + oh2; oh = g_fwvTh + oh2; ol = g_fwvTl + oh2;
    }
  }
  __shared__ float tile[32][33];
  int r0 = tr*32, c0 = tc*32;
  int x = c0 + threadIdx.x;
  for(int dy = threadIdx.y; dy < 32; dy += 8)
    tile[dy][threadIdx.x] = in[(long)(r0 + dy)*C + x];
  __syncthreads();
  int xo = r0 + threadIdx.x;
  for(int dy = threadIdx.y; dy < 32; dy += 8){
    float v = tile[threadIdx.x][dy];
    bf h = __float2bfloat16(v);
    long oidx = (long)(c0 + dy)*R + xo;
    oh[oidx] = h; ol[oidx] = __float2bfloat16(v - __bfloat162float(h));
  }
}

// ---------------- im2col, split output ---------------------------------------
__global__ void im2col2_k(){
  int t = blockIdx.x*256 + threadIdx.x;
  int k4 = t % (K2C/4); int m = t / (K2C/4);
  int k = k4*4;
  int r = k >> 7; int ci = k & 127;
  int kh = r / 3, kw = r % 3;
  int wo = m % W2; int rest = m / W2;
  int ho = rest % H2; int b = rest / H2;
  int hi = 2*ho + kh - 1, wi = 2*wo + kw - 1;
  float4 v = make_float4(0.f,0.f,0.f,0.f);
  if(hi >= 0 && hi < H1 && wi >= 0 && wi < W1)
    v = *(const float4*)&g_conv1[((b*H1 + hi)*W1 + wi)*C1 + ci];
  uint2 hh, ll;
  split4(v, hh, ll);
  long dst = (long)m*K2C + k;
  *(uint2*)&g_col2h[dst] = hh;
  *(uint2*)&g_col2l[dst] = ll;
}
__global__ void im2col3_k(){
  int t = blockIdx.x*256 + threadIdx.x;
  int k4 = t % (K3C/4); int m = t / (K3C/4);
  int k = k4*4;
  int r = k >> 8; int ci = k & 255;
  int kh = r / 3, kw = r % 3;
  int wo = m % W2; int rest = m / W2;
  int ho = rest % H2; int b = rest / H2;
  int hi = ho + kh - 1, wi = wo + kw - 1;
  uint2 vh = make_uint2(0,0), vl = make_uint2(0,0);
  if(hi >= 0 && hi < H2 && wi >= 0 && wi < W2){
    long src = (long)((b*H2 + hi)*W2 + wi)*C2 + ci;
    vh = *(const uint2*)&g_c2h[src];
    vl = *(const uint2*)&g_c2l[src];
  }
  long dst = (long)m*K3C + k;
  *(uint2*)&g_col3h[dst] = vh;
  *(uint2*)&g_col3l[dst] = vl;
}

// ---------------- reshape ------------------------------------------------------
__global__ void reshape_k(){
  __shared__ uint16_t smh[KE], sml[KE];
  int m = blockIdx.x;
  const uint16_t* srch = (const uint16_t*)g_c3h + (long)m*KE;
  const uint16_t* srcl = (const uint16_t*)g_c3l + (long)m*KE;
  for(int i=threadIdx.x; i<KE; i+=256){
    int w = i / 512, c = i & 511;
    int d = c*W2 + w;
    smh[d] = srch[i];
    sml[d] = srcl[i];
  }
  __syncthreads();
  uint16_t* dsth = (uint16_t*)g_yrh + (long)m*KE;
  uint16_t* dstl = (uint16_t*)g_yrl + (long)m*KE;
  for(int i=threadIdx.x; i<KE; i+=256){ dsth[i] = smh[i]; dstl[i] = sml[i]; }
}

// ---------------- LayerNorm ----------------------------------------------------
__global__ void ln_k(const float* __restrict__ x, const float* __restrict__ gw,
                     const float* __restrict__ gb, float* __restrict__ o){
  int m = blockIdx.x;
  int tid = threadIdx.x;
  const float* xr = x + (long)m*DIM;
  float v[4]; float s = 0.f, sq = 0.f;
  #pragma unroll
  for(int j=0;j<4;j++){ float t = xr[tid + j*128]; v[j] = t; s += t; sq += t*t; }
  #pragma unroll
  for(int off=16; off; off>>=1){
    s  += __shfl_xor_sync(0xffffffffu, s,  off);
    sq += __shfl_xor_sync(0xffffffffu, sq, off);
  }
  __shared__ float ss[4], sqs[4];
  if((tid & 31) == 0){ ss[tid>>5] = s; sqs[tid>>5] = sq; }
  __syncthreads();
  s  = (ss[0]+ss[1]) + (ss[2]+ss[3]);
  sq = (sqs[0]+sqs[1]) + (sqs[2]+sqs[3]);
  float mean = s * (1.f/DIM);
  float var  = sq * (1.f/DIM) - mean*mean;
  float rstd = rsqrtf(var + 1e-5f);
  float* orow = o + (long)m*DIM;
  #pragma unroll
  for(int j=0;j<4;j++){
    int d = tid + j*128;
    orow[d] = (v[j] - mean)*rstd*gw[d] + gb[d];
  }
}

// ---------------- time-shift mixes ---------------------------------------------
__global__ void mix3_k(const float* __restrict__ xn, const float* __restrict__ mk,
                       const float* __restrict__ mv, const float* __restrict__ mr){
  int g = blockIdx.x*256 + threadIdx.x;
  int t = g*2;
  int d = t & (DIM-1);
  int tok = (t >> 9) & (USEQ-1);
  float2 cur = *(const float2*)&xn[t];
  float2 sh = tok ? *(const float2*)&xn[t - DIM] : make_float2(0.f, 0.f);
  float d0 = cur.x - sh.x, d1 = cur.y - sh.y;
  uint32_t h, l;
  split2(fmaf(d0, mk[d], sh.x), fmaf(d1, mk[d+1], sh.y), h, l);
  *(uint32_t*)&g_xkh[t] = h; *(uint32_t*)&g_xkl[t] = l;
  split2(fmaf(d0, mv[d], sh.x), fmaf(d1, mv[d+1], sh.y), h, l);
  *(uint32_t*)&g_xvh[t] = h; *(uint32_t*)&g_xvl[t] = l;
  split2(fmaf(d0, mr[d], sh.x), fmaf(d1, mr[d+1], sh.y), h, l);
  *(uint32_t*)&g_xrh[t] = h; *(uint32_t*)&g_xrl[t] = l;
}
__global__ void mix2_k(const float* __restrict__ xn, const float* __restrict__ mk,
                       const float* __restrict__ mr){
  int g = blockIdx.x*256 + threadIdx.x;
  int t = g*2;
  int d = t & (DIM-1);
  int tok = (t >> 9) & (USEQ-1);
  float2 cur = *(const float2*)&xn[t];
  float2 sh = tok ? *(const float2*)&xn[t - DIM] : make_float2(0.f, 0.f);
  float d0 = cur.x - sh.x, d1 = cur.y - sh.y;
  uint32_t h, l;
  split2(fmaf(d0, mk[d], sh.x), fmaf(d1, mk[d+1], sh.y), h, l);
  *(uint32_t*)&g_xkh[t] = h; *(uint32_t*)&g_xkl[t] = l;
  split2(fmaf(d0, mr[d], sh.x), fmaf(d1, mr[d+1], sh.y), h, l);
  *(uint32_t*)&g_xrh[t] = h; *(uint32_t*)&g_xrl[t] = l;
}

// ---------------- WKV scan, pipelined, bf16 split output -----------------------
#define WG 8
__device__ __forceinline__ void wkv_load(const float* kp, const float* vp,
                                         const float* rp, long off0,
                                         float* kb, float* vb, float* rb){
  #pragma unroll
  for(int j=0;j<WG;j++){
    long off = off0 + (long)j*DIM;
    kb[j] = __ldg(kp + off); vb[j] = __ldg(vp + off); rb[j] = __ldg(rp + off);
  }
}
__device__ __forceinline__ void wkv_step(float* kb, float* vb, float* rb,
                                         bf* oh, bf* ol, long off0,
                                         float w, float u,
                                         float& aa, float& bb, float& pp){
  #pragma unroll
  for(int j=0;j<WG;j++){
    float kt = kb[j], vt = vb[j];
    float ww = u + kt;
    float p  = fmaxf(pp, ww);
    float e1 = __expf(pp - p), e2 = __expf(ww - p);
    float o  = rb[j] * (e1*aa + e2*vt) / (e1*bb + e2);
    bf h = __float2bfloat16(o);
    long off = off0 + (long)j*DIM;
    oh[off] = h;
    ol[off] = __float2bfloat16(o - __bfloat162float(h));
    float ww2 = pp + w;
    float p2  = fmaxf(ww2, kt);
    e1 = __expf(ww2 - p2); e2 = __expf(kt - p2);
    aa = e1*aa + e2*vt; bb = e1*bb + e2; pp = p2;
  }
}
__global__ void wkv_k(const float* __restrict__ k, const float* __restrict__ v,
                      const float* __restrict__ r,
                      const float* __restrict__ dec, const float* __restrict__ fir){
  int t = blockIdx.x*blockDim.x + threadIdx.x;
  int d = t & (DIM-1); int b = t >> 9;
  float w = -__expf(dec[d]);
  float u = fir[d];
  float aa = 0.f, bb = 0.f, pp = -1e38f;
  long base = (long)b*USEQ*DIM + d;
  const float* kp = k + base;
  const float* vp = v + base;
  const float* rp = r + base;
  bf* oh = g_rwh + base;
  bf* ol = g_rwl + base;
  const int NG = USEQ/WG;
  float k0b[WG], v0b[WG], r0b[WG];
  float k1b[WG], v1b[WG], r1b[WG];
  wkv_load(kp, vp, rp, 0, k0b, v0b, r0b);
  for(int g=0; g<NG; g+=2){
    long off1 = (long)(g+1)*WG*DIM;
    wkv_load(kp, vp, rp, off1, k1b, v1b, r1b);
    wkv_step(k0b, v0b, r0b, oh, ol, (long)g*WG*DIM, w, u, aa, bb, pp);
    if(g+2 < NG){
      long off2 = (long)(g+2)*WG*DIM;
      wkv_load(kp, vp, rp, off2, k0b, v0b, r0b);
    }
    wkv_step(k1b, v1b, r1b, oh, ol, off1, w, u, aa, bb, pp);
  }
}

// ---------------- olens tail ----------------------------------------------------
__global__ void tail_k(const int* __restrict__ x_len, float* __restrict__ out, int out_size){
  int b = threadIdx.x;
  if(b < BATCH && out_size >= HTOK + BATCH){
    int l1 = (x_len[b] - 1)/2 + 1;
    int ol = (l1 - 1)/2 + 1;
    out[HTOK + b] = (float)ol;
  }
}

// ---------------- host side -----------------------------------------------------
template <typename T>
static void* symaddr(const T& s){ void* p = nullptr; cudaGetSymbolAddress(&p, s); return p; }

template<int ACT, int EPI, int OUT>
static void gemm(int M, int N, int K, const bf* Ah, const bf* Al,
                 const bf* Bh, const bf* Bl, const float* bias,
                 float* C, bf* Ch, bf* Cl, const float* mul){
  cudaFuncSetAttribute(mgemm_k<ACT,EPI,OUT>, cudaFuncAttributeMaxDynamicSharedMemorySize, MSMEM);
  dim3 grid(N/128, M/128);
  mgemm_k<ACT,EPI,OUT><<<grid, 512, MSMEM>>>(M, N, K, Ah, Al, Bh, Bl, bias, C, Ch, Cl, mul);
}

extern "C" void kernel_launch(void* const* d_in, const int* in_sizes, int n_in,
                              void* d_out, int out_size){
  const float* x       = (const float*)d_in[0];
  const int*   x_len   = (const int*)  d_in[1];
  const float* conv1_w = (const float*)d_in[2];
  const float* conv1_b = (const float*)d_in[3];
  const float* conv2_w = (const float*)d_in[4];
  const float* conv2_b = (const float*)d_in[5];
  const float* conv3_w = (const float*)d_in[6];
  const float* conv3_b = (const float*)d_in[7];
  const float* embed_w = (const float*)d_in[8];
  const float* embed_b = (const float*)d_in[9];
  const float* eln_g   = (const float*)d_in[10];
  const float* eln_b   = (const float*)d_in[11];
  const float* lag     = (const float*)d_in[12];
  const float* lab     = (const float*)d_in[13];
  const float* dec     = (const float*)d_in[14];
  const float* fir     = (const float*)d_in[15];
  const float* amk     = (const float*)d_in[16];
  const float* amv     = (const float*)d_in[17];
  const float* amr     = (const float*)d_in[18];
  const float* awk     = (const float*)d_in[19];
  const float* awv     = (const float*)d_in[20];
  const float* awr     = (const float*)d_in[21];
  const float* awo     = (const float*)d_in[22];
  const float* lfg     = (const float*)d_in[23];
  const float* lfb     = (const float*)d_in[24];
  const float* fmk     = (const float*)d_in[25];
  const float* fmr     = (const float*)d_in[26];
  const float* fwk     = (const float*)d_in[27];
  const float* fwv     = (const float*)d_in[28];
  const float* fwr     = (const float*)d_in[29];
  const float* flg     = (const float*)d_in[30];
  const float* flb     = (const float*)d_in[31];
  float* out = (float*)d_out;

  bf* p_col2h = (bf*)symaddr(g_col2h); bf* p_col2l = (bf*)symaddr(g_col2l);
  bf* p_c2h   = (bf*)symaddr(g_c2h);   bf* p_c2l   = (bf*)symaddr(g_c2l);
  bf* p_col3h = (bf*)symaddr(g_col3h); bf* p_col3l = (bf*)symaddr(g_col3l);
  bf* p_c3h   = (bf*)symaddr(g_c3h);   bf* p_c3l   = (bf*)symaddr(g_c3l);
  bf* p_yrh   = (bf*)symaddr(g_yrh);   bf* p_yrl   = (bf*)symaddr(g_yrl);
  float* p_t0 = (float*)symaddr(g_t0);
  float* p_h  = (float*)symaddr(g_h);
  float* p_xn = (float*)symaddr(g_xn);
  bf* p_xkh = (bf*)symaddr(g_xkh); bf* p_xkl = (bf*)symaddr(g_xkl);
  bf* p_xvh = (bf*)symaddr(g_xvh); bf* p_xvl = (bf*)symaddr(g_xvl);
  bf* p_xrh = (bf*)symaddr(g_xrh); bf* p_xrl = (bf*)symaddr(g_xrl);
  float* p_k = (float*)symaddr(g_k);
  float* p_v = (float*)symaddr(g_v);
  float* p_r = (float*)symaddr(g_r);
  bf* p_rwh = (bf*)symaddr(g_rwh); bf* p_rwl = (bf*)symaddr(g_rwl);
  bf* p_kkh = (bf*)symaddr(g_kkh); bf* p_kkl = (bf*)symaddr(g_kkl);
  bf* p_w2Th = (bf*)symaddr(g_w2Th); bf* p_w2Tl = (bf*)symaddr(g_w2Tl);
  bf* p_w3Th = (bf*)symaddr(g_w3Th); bf* p_w3Tl = (bf*)symaddr(g_w3Tl);
  bf* p_ewTh = (bf*)symaddr(g_ewTh); bf* p_ewTl = (bf*)symaddr(g_ewTl);
  bf* p_aqkvTh = (bf*)symaddr(g_aqkvTh); bf* p_aqkvTl = (bf*)symaddr(g_aqkvTl);
  bf* p_awoTh  = (bf*)symaddr(g_awoTh);  bf* p_awoTl  = (bf*)symaddr(g_awoTl);
  bf* p_fkrTh  = (bf*)symaddr(g_fkrTh);  bf* p_fkrTl  = (bf*)symaddr(g_fkrTl);
  bf* p_fwvTh  = (bf*)symaddr(g_fwvTh);  bf* p_fwvTl  = (bf*)symaddr(g_fwvTl);

  // launches 1-6 (launch 6 = conv3 GEMM profiled by ncu -s 5 -c 1)
  prep_conv_k<<<(C2*K2C + C3*K3C + 255)/256, 256>>>(conv2_w, conv3_w);
  conv1_k<<<(BATCH*H1*W1*C1)/256, 256>>>(x, conv1_w, conv1_b);
  im2col2_k<<<(MCONV*(K2C/4))/256, 256>>>();
  gemm<1,0,1>(MCONV, C2, K2C, p_col2h, p_col2l, p_w2Th, p_w2Tl, conv2_b,
              nullptr, p_c2h, p_c2l, nullptr);
  im2col3_k<<<(MCONV*(K3C/4))/256, 256>>>();
  gemm<1,0,1>(MCONV, C3, K3C, p_col3h, p_col3l, p_w3Th, p_w3Tl, conv3_b,
              nullptr, p_c3h, p_c3l, nullptr);

  prep_big_k<<<18432, dim3(32,8)>>>(embed_w, awk, awv, awr, awo, fwr, fwk, fwv);
  reshape_k<<<MT, 256>>>();
  gemm<0,0,0>(MT, DIM, KE, p_yrh, p_yrl, p_ewTh, p_ewTl, embed_b,
              p_t0, nullptr, nullptr, nullptr);
  ln_k<<<MT, 128>>>(p_t0, eln_g, eln_b, p_h);

  // ---- RWKV blocks ----
  for(int i = 0; i < NB_; i++){
    long w2 = (long)i*DIM*DIM;
    long wh = (long)i*DIM*HID;
    long qb = (long)i*3*DIM*DIM;
    long fb = (long)i*(HID+DIM)*DIM;
    // time mixing
    ln_k<<<MT, 128>>>(p_h, lag + i*DIM, lab + i*DIM, p_xn);
    mix3_k<<<HTOK/512, 256>>>(p_xn, amk + i*DIM, amv + i*DIM, amr + i*DIM);
    gemm<0,0,0>(MT, DIM, DIM, p_xkh, p_xkl, p_aqkvTh + qb, p_aqkvTl + qb, nullptr,
                p_k, nullptr, nullptr, nullptr);
    gemm<0,0,0>(MT, DIM, DIM, p_xvh, p_xvl, p_aqkvTh + qb + (long)DIM*DIM,
                p_aqkvTl + qb + (long)DIM*DIM, nullptr,
                p_v, nullptr, nullptr, nullptr);
    gemm<2,0,0>(MT, DIM, DIM, p_xrh, p_xrl, p_aqkvTh + qb + 2L*DIM*DIM,
                p_aqkvTl + qb + 2L*DIM*DIM, nullptr,
                p_r, nullptr, nullptr, nullptr);
    wkv_k<<<(BATCH*DIM)/32, 32>>>(p_k, p_v, p_r, dec + i*DIM, fir + i*DIM);
    gemm<0,1,0>(MT, DIM, DIM, p_rwh, p_rwl, p_awoTh + w2, p_awoTl + w2, nullptr,
                p_h, nullptr, nullptr, nullptr);
    // channel mixing
    ln_k<<<MT, 128>>>(p_h, lfg + i*DIM, lfb + i*DIM, p_xn);
    mix2_k<<<HTOK/512, 256>>>(p_xn, fmk + i*DIM, fmr + i*DIM);
    gemm<3,0,1>(MT, HID, DIM, p_xkh, p_xkl, p_fkrTh + fb, p_fkrTl + fb, nullptr,
                nullptr, p_kkh, p_kkl, nullptr);
    gemm<2,0,0>(MT, DIM, DIM, p_xrh, p_xrl, p_fkrTh + fb + (long)HID*DIM,
                p_fkrTl + fb + (long)HID*DIM, nullptr,
                p_r, nullptr, nullptr, nullptr);
    gemm<0,2,0>(MT, DIM, HID, p_kkh, p_kkl, p_fwvTh + wh, p_fwvTl + wh, nullptr,
                p_h, nullptr, nullptr, p_r);
  }

  ln_k<<<MT, 128>>>(p_h, flg, flb, out);
  tail_k<<<1, 32>>>(x_len, out, out_size);
}

// round 10
// speedup vs baseline: 1.3005x; 1.3005x over previous
#include <cuda_runtime.h>
#include <cuda_bf16.h>
#include <cstdint>

typedef __nv_bfloat16 bf;

#define NB_   4
#define BATCH 8
#define LEN   4096
#define FREQ  80
#define DIM   512
#define HID   2048
#define USEQ  1024
#define C1    128
#define C2    256
#define C3    512
#define H1    2048
#define W1    40
#define H2    1024
#define W2    20
#define MCONV (BATCH*H2*W2)      /* 163840 */
#define K2C   (9*C1)             /* 1152 */
#define K3C   (9*C2)             /* 2304 */
#define KE    (C3*W2)            /* 10240 */
#define MT    (BATCH*USEQ)       /* 8192 */
#define HTOK  (MT*DIM)           /* 4194304 */

// ---------------- scratch (device globals; no allocations) ----------------
__device__ float g_conv1[BATCH*H1*W1*C1];
__device__ bf g_col2h[MCONV*K2C],  g_col2l[MCONV*K2C];
__device__ bf g_c2h[MCONV*C2],     g_c2l[MCONV*C2];
__device__ bf g_col3h[MCONV*K3C],  g_col3l[MCONV*K3C];
__device__ bf g_c3h[MCONV*C3],     g_c3l[MCONV*C3];
__device__ bf g_yrh[MT*KE],        g_yrl[MT*KE];
__device__ float g_t0[HTOK];
__device__ float g_h[HTOK];
__device__ float g_xn[HTOK];
__device__ bf g_xkh[HTOK], g_xkl[HTOK];
__device__ bf g_xvh[HTOK], g_xvl[HTOK];
__device__ bf g_xrh[HTOK], g_xrl[HTOK];
__device__ float g_k[HTOK];
__device__ float g_v[HTOK];
__device__ float g_r[HTOK];
__device__ bf g_rwh[HTOK], g_rwl[HTOK];
__device__ bf g_kkh[MT*HID], g_kkl[MT*HID];
// transposed+split weights, [N][K] K-major bf16 hi/lo
__device__ bf g_w2Th[C2*K2C],  g_w2Tl[C2*K2C];
__device__ bf g_w3Th[C3*K3C],  g_w3Tl[C3*K3C];
__device__ bf g_ewTh[DIM*KE],  g_ewTl[DIM*KE];
__device__ bf g_aqkvTh[NB_*3*DIM*DIM], g_aqkvTl[NB_*3*DIM*DIM];
__device__ bf g_awoTh[NB_*DIM*DIM],    g_awoTl[NB_*DIM*DIM];
__device__ bf g_fkrTh[NB_*(HID+DIM)*DIM], g_fkrTl[NB_*(HID+DIM)*DIM];
__device__ bf g_fwvTh[NB_*DIM*HID],    g_fwvTl[NB_*DIM*HID];

// ================== helpers ==================
__device__ __forceinline__ uint32_t smem_to_u32(const void* p) {
  uint32_t a;
  asm("{ .reg .u64 t; cvta.to.shared.u64 t, %1; cvt.u32.u64 %0, t; }"
      : "=r"(a) : "l"(p));
  return a;
}
__device__ __forceinline__ void ldsm4(uint32_t* r, uint32_t addr){
  asm volatile("ldmatrix.sync.aligned.m8n8.x4.shared.b16 {%0,%1,%2,%3}, [%4];"
    : "=r"(r[0]),"=r"(r[1]),"=r"(r[2]),"=r"(r[3]) : "r"(addr));
}
__device__ __forceinline__ void mma_bf16(float* d, const uint32_t* a, const uint32_t* b){
  asm volatile("mma.sync.aligned.m16n8k16.row.col.f32.bf16.bf16.f32 "
    "{%0,%1,%2,%3}, {%4,%5,%6,%7}, {%8,%9}, {%0,%1,%2,%3};"
    : "+f"(d[0]),"+f"(d[1]),"+f"(d[2]),"+f"(d[3])
    : "r"(a[0]),"r"(a[1]),"r"(a[2]),"r"(a[3]), "r"(b[0]),"r"(b[1]));
}
__device__ __forceinline__ void cp16(uint32_t s, const void* g){
  asm volatile("cp.async.cg.shared.global [%0], [%1], 16;" :: "r"(s), "l"(g));
}
#define CP_COMMIT() asm volatile("cp.async.commit_group;" ::: "memory")
#define CP_WAIT1()  asm volatile("cp.async.wait_group 1;" ::: "memory")

__device__ __forceinline__ void split2(float v0, float v1, uint32_t& h, uint32_t& l){
  __nv_bfloat162 hh = __floats2bfloat162_rn(v0, v1);
  float r0 = v0 - __bfloat162float(hh.x);
  float r1 = v1 - __bfloat162float(hh.y);
  __nv_bfloat162 ll = __floats2bfloat162_rn(r0, r1);
  h = *(uint32_t*)&hh; l = *(uint32_t*)&ll;
}
__device__ __forceinline__ void split4(float4 v, uint2& hi, uint2& lo){
  split2(v.x, v.y, hi.x, lo.x);
  split2(v.z, v.w, hi.y, lo.y);
}
__device__ __forceinline__ float sgm(float v){ return 1.f/(1.f + __expf(-v)); }

// ====== bf16x3 MMA GEMM: CTA 128x256, Kchunk=32, 8 warps (64x64 tiles) =======
// 3-stage cp.async pipeline. C = epi(act(A @ Wt^T + bias))
// ACT: 0 none,1 relu,2 sigmoid,3 relu^2 ; EPI: 0 store,1 +=,2 C+mul*acc
// OUT: 0 fp32 C ; 1 bf16 split Ch/Cl
#define PITCH 40
#define AHI_O 0
#define ALO_O 10240
#define BHI_O 20480
#define BLO_O 40960
#define STG_B 61440
#define MSMEM (3*STG_B)

template<int ACT, int EPI, int OUT>
__global__ void __launch_bounds__(256, 1) mgemm_k(int M, int N, int K,
    const bf* __restrict__ Ah, const bf* __restrict__ Al,
    const bf* __restrict__ Bh, const bf* __restrict__ Bl,
    const float* __restrict__ bias, float* __restrict__ C,
    bf* __restrict__ Ch, bf* __restrict__ Cl, const float* __restrict__ mul){
  extern __shared__ char smarr[];
  uint32_t smb = smem_to_u32(smarr);
  int tid = threadIdx.x, lane = tid & 31, wid = tid >> 5;
  int wm = wid >> 2, wn = wid & 3;          // warp grid 2(m) x 4(n), tiles 64x64
  long m0 = (long)blockIdx.y * 128;
  int  n0 = blockIdx.x * 256;

  // loader: 3072 16B segments/chunk (768 row-quarters). seg = tid + i*256, i<12
  // row r: 0-127 Ah, 128-255 Al, 256-511 Bh, 512-767 Bl; 4 segs (w=0..3)/row.
  const bf* lgp[12];
  uint32_t lsoff[12];
  #pragma unroll
  for(int i = 0; i < 12; i++){
    int seg = tid + i*256;
    int r = seg >> 2, w = seg & 3;
    const bf* gp; uint32_t ao; int row;
    if(r < 128)      { gp = Ah; ao = AHI_O; row = r;       gp += (m0 + row)*(long)K; }
    else if(r < 256) { gp = Al; ao = ALO_O; row = r - 128; gp += (m0 + row)*(long)K; }
    else if(r < 512) { gp = Bh; ao = BHI_O; row = r - 256; gp += ((long)n0 + row)*K; }
    else             { gp = Bl; ao = BLO_O; row = r - 512; gp += ((long)n0 + row)*K; }
    lgp[i] = gp + w*8;
    lsoff[i] = ao + (uint32_t)row*80 + w*16;
  }

  // ldmatrix per-lane byte offsets (within hi arrays; lo at +delta)
  uint32_t aoff = (((uint32_t)wm*64 + ((lane>>3)&1)*8 + (lane&7))*PITCH + ((lane>>4)&1)*8) * 2;
  uint32_t boff = (((uint32_t)wn*64 + ((lane>>4)&1)*8 + (lane&7))*PITCH + ((lane>>3)&1)*8) * 2;

  float acc[4][8][4];
  #pragma unroll
  for(int i=0;i<4;i++)
    #pragma unroll
    for(int j=0;j<8;j++)
      #pragma unroll
      for(int q=0;q<4;q++) acc[i][j][q] = 0.f;

  int nc = K >> 5;

  #define LOAD_CHUNK(c, sidx) do { \
    uint32_t stg_ = smb + (sidx)*STG_B; \
    long go_ = (long)(c)*32; \
    _Pragma("unroll") \
    for(int i_ = 0; i_ < 12; i_++) cp16(stg_ + lsoff[i_], lgp[i_] + go_); \
  } while(0)

  LOAD_CHUNK(0, 0); CP_COMMIT();
  LOAD_CHUNK(1, 1); CP_COMMIT();

  for(int c = 0; c < nc; c++){
    CP_WAIT1();
    __syncthreads();
    if(c + 2 < nc){ LOAD_CHUNK(c + 2, (c + 2) % 3); }
    CP_COMMIT();
    uint32_t stg = smb + (c % 3)*STG_B;
    #pragma unroll
    for(int ks = 0; ks < 2; ks++){
      uint32_t ahk[4][4], alk[4][4], bhk[4][4], blk[4][4];
      #pragma unroll
      for(int mt = 0; mt < 4; mt++){
        uint32_t ad = stg + AHI_O + aoff + mt*(16*PITCH*2) + ks*32;
        ldsm4(ahk[mt], ad);
        ldsm4(alk[mt], ad + (ALO_O - AHI_O));
      }
      #pragma unroll
      for(int ng = 0; ng < 4; ng++){
        uint32_t bd = stg + BHI_O + boff + ng*(16*PITCH*2) + ks*32;
        ldsm4(bhk[ng], bd);
        ldsm4(blk[ng], bd + (BLO_O - BHI_O));
      }
      #pragma unroll
      for(int mt = 0; mt < 4; mt++)
        #pragma unroll
        for(int nt = 0; nt < 8; nt++)
          mma_bf16(acc[mt][nt], ahk[mt], &bhk[nt>>1][(nt&1)*2]);
      #pragma unroll
      for(int mt = 0; mt < 4; mt++)
        #pragma unroll
        for(int nt = 0; nt < 8; nt++)
          mma_bf16(acc[mt][nt], ahk[mt], &blk[nt>>1][(nt&1)*2]);
      #pragma unroll
      for(int mt = 0; mt < 4; mt++)
        #pragma unroll
        for(int nt = 0; nt < 8; nt++)
          mma_bf16(acc[mt][nt], alk[mt], &bhk[nt>>1][(nt&1)*2]);
    }
  }

  // ---- epilogue ----
  int mrow = lane >> 2;
  int ncol = (lane & 3) * 2;
  #pragma unroll
  for(int mt = 0; mt < 4; mt++){
    #pragma unroll
    for(int nt = 0; nt < 8; nt++){
      #pragma unroll
      for(int hf = 0; hf < 2; hf++){
        long gm = m0 + wm*64 + mt*16 + mrow + hf*8;
        int  gn = n0 + wn*64 + nt*8 + ncol;
        float v0 = acc[mt][nt][hf*2+0];
        float v1 = acc[mt][nt][hf*2+1];
        if(bias){ v0 += bias[gn]; v1 += bias[gn+1]; }
        if(ACT == 1){ v0 = fmaxf(v0,0.f); v1 = fmaxf(v1,0.f); }
        else if(ACT == 2){ v0 = sgm(v0); v1 = sgm(v1); }
        else if(ACT == 3){ v0 = fmaxf(v0,0.f); v0 *= v0; v1 = fmaxf(v1,0.f); v1 *= v1; }
        if(OUT == 0){
          float* cp = C + gm*N + gn;
          if(EPI == 1){ v0 += cp[0]; v1 += cp[1]; }
          else if(EPI == 2){
            const float* mp = mul + gm*N + gn;
            v0 = cp[0] + mp[0]*v0; v1 = cp[1] + mp[1]*v1;
          }
          *(float2*)cp = make_float2(v0, v1);
        } else {
          uint32_t hh, ll;
          split2(v0, v1, hh, ll);
          *(uint32_t*)&Ch[gm*N + gn] = hh;
          *(uint32_t*)&Cl[gm*N + gn] = ll;
        }
      }
    }
  }
}

// ---------------- conv1 ------------------------------------------------------
__global__ void conv1_k(const float* __restrict__ x, const float* __restrict__ w,
                        const float* __restrict__ bias){
  int t = blockIdx.x*256 + threadIdx.x;
  int co = t & 127;
  int rest = t >> 7;
  int wo = rest % W1; rest /= W1;
  int ho = rest % H1; int b = rest / H1;
  float acc = bias[co];
  int hi0 = 2*ho - 1, wi0 = 2*wo - 1;
  #pragma unroll
  for(int kh=0; kh<3; kh++){
    int hi = hi0 + kh;
    if(hi < 0 || hi >= LEN) continue;
    #pragma unroll
    for(int kw=0; kw<3; kw++){
      int wi = wi0 + kw;
      if(wi < 0 || wi >= FREQ) continue;
      acc = fmaf(x[(hi + (long)b*LEN)*FREQ + wi], w[co*9 + kh*3 + kw], acc);
    }
  }
  g_conv1[t] = fmaxf(acc, 0.f);
}

// ---------------- conv weight prep -------------------------------------------
__global__ void prep_conv_k(const float* __restrict__ w2, const float* __restrict__ w3){
  int t = blockIdx.x*256 + threadIdx.x;
  if(t < C2*K2C){
    int co = t / K2C; int idx = t % K2C;
    int r = idx / C1; int ci = idx % C1;
    float v = w2[co*(C1*9) + ci*9 + r];
    bf h = __float2bfloat16(v);
    g_w2Th[t] = h; g_w2Tl[t] = __float2bfloat16(v - __bfloat162float(h));
  } else {
    int u = t - C2*K2C;
    if(u >= C3*K3C) return;
    int co = u / K3C; int idx = u % K3C;
    int r = idx / C2; int ci = idx % C2;
    float v = w3[co*(C2*9) + ci*9 + r];
    bf h = __float2bfloat16(v);
    g_w3Th[u] = h; g_w3Tl[u] = __float2bfloat16(v - __bfloat162float(h));
  }
}

// ------ big weight prep: transpose [R][C]->[C][R] + split + concat -----------
__global__ void prep_big_k(const float* __restrict__ embed_w,
                           const float* __restrict__ awk, const float* __restrict__ awv,
                           const float* __restrict__ awr, const float* __restrict__ awo,
                           const float* __restrict__ fwr, const float* __restrict__ fwk,
                           const float* __restrict__ fwv){
  int t = blockIdx.x;
  const float* in; bf *oh, *ol; int R, C, tr, tc;
  if(t < 5120){
    in = embed_w; oh = g_ewTh; ol = g_ewTl; R = KE; C = DIM;
    tr = t / 16; tc = t % 16;
  } else {
    int u = t - 5120;
    int i = u / 3328; int v = u % 3328;
    long o2 = (long)i*DIM*DIM, oh2 = (long)i*DIM*HID;
    long qb = (long)i*3*DIM*DIM, fb = (long)i*(HID+DIM)*DIM;
    if(v < 768){
      int kind = v / 256; int vv = v % 256;
      R = DIM; C = DIM; tr = vv / 16; tc = vv % 16;
      in = (kind == 0 ? awk : kind == 1 ? awv : awr) + o2;
      oh = g_aqkvTh + qb + (long)kind*DIM*DIM;
      ol = g_aqkvTl + qb + (long)kind*DIM*DIM;
    } else if(v < 1024){
      int vv = v - 768;
      R = DIM; C = DIM; tr = vv / 16; tc = vv % 16;
      in = awo + o2; oh = g_awoTh + o2; ol = g_awoTl + o2;
    } else if(v < 2048){
      int vv = v - 1024;
      R = DIM; C = HID; tr = vv / 64; tc = vv % 64;
      in = fwk + oh2; oh = g_fkrTh + fb; ol = g_fkrTl + fb;
    } else if(v < 2304){
      int vv = v - 2048;
      R = DIM; C = DIM; tr = vv / 16; tc = vv % 16;
      in = fwr + o2;
      oh = g_fkrTh + fb + (long)HID*DIM;
      ol = g_fkrTl + fb + (long)HID*DIM;
    } else {
      int vv = v - 2304;
      R = HID; C = DIM; tr = vv / 16; tc = vv % 16;
      in = fwv + oh2; oh = g_fwvTh + oh2; ol = g_fwvTl + oh2;
    }
  }
  __shared__ float tile[32][33];
  int r0 = tr*32, c0 = tc*32;
  int x = c0 + threadIdx.x;
  for(int dy = threadIdx.y; dy < 32; dy += 8)
    tile[dy][threadIdx.x] = in[(long)(r0 + dy)*C + x];
  __syncthreads();
  int xo = r0 + threadIdx.x;
  for(int dy = threadIdx.y; dy < 32; dy += 8){
    float v = tile[threadIdx.x][dy];
    bf h = __float2bfloat16(v);
    long oidx = (long)(c0 + dy)*R + xo;
    oh[oidx] = h; ol[oidx] = __float2bfloat16(v - __bfloat162float(h));
  }
}

// ---------------- im2col, split output ---------------------------------------
__global__ void im2col2_k(){
  int t = blockIdx.x*256 + threadIdx.x;
  int k4 = t % (K2C/4); int m = t / (K2C/4);
  int k = k4*4;
  int r = k >> 7; int ci = k & 127;
  int kh = r / 3, kw = r % 3;
  int wo = m % W2; int rest = m / W2;
  int ho = rest % H2; int b = rest / H2;
  int hi = 2*ho + kh - 1, wi = 2*wo + kw - 1;
  float4 v = make_float4(0.f,0.f,0.f,0.f);
  if(hi >= 0 && hi < H1 && wi >= 0 && wi < W1)
    v = *(const float4*)&g_conv1[((b*H1 + hi)*W1 + wi)*C1 + ci];
  uint2 hh, ll;
  split4(v, hh, ll);
  long dst = (long)m*K2C + k;
  *(uint2*)&g_col2h[dst] = hh;
  *(uint2*)&g_col2l[dst] = ll;
}
__global__ void im2col3_k(){
  int t = blockIdx.x*256 + threadIdx.x;
  int k4 = t % (K3C/4); int m = t / (K3C/4);
  int k = k4*4;
  int r = k >> 8; int ci = k & 255;
  int kh = r / 3, kw = r % 3;
  int wo = m % W2; int rest = m / W2;
  int ho = rest % H2; int b = rest / H2;
  int hi = ho + kh - 1, wi = wo + kw - 1;
  uint2 vh = make_uint2(0,0), vl = make_uint2(0,0);
  if(hi >= 0 && hi < H2 && wi >= 0 && wi < W2){
    long src = (long)((b*H2 + hi)*W2 + wi)*C2 + ci;
    vh = *(const uint2*)&g_c2h[src];
    vl = *(const uint2*)&g_c2l[src];
  }
  long dst = (long)m*K3C + k;
  *(uint2*)&g_col3h[dst] = vh;
  *(uint2*)&g_col3l[dst] = vl;
}

// ---------------- reshape ------------------------------------------------------
__global__ void reshape_k(){
  __shared__ uint16_t smh[KE], sml[KE];
  int m = blockIdx.x;
  const uint16_t* srch = (const uint16_t*)g_c3h + (long)m*KE;
  const uint16_t* srcl = (const uint16_t*)g_c3l + (long)m*KE;
  for(int i=threadIdx.x; i<KE; i+=256){
    int w = i / 512, c = i & 511;
    int d = c*W2 + w;
    smh[d] = srch[i];
    sml[d] = srcl[i];
  }
  __syncthreads();
  uint16_t* dsth = (uint16_t*)g_yrh + (long)m*KE;
  uint16_t* dstl = (uint16_t*)g_yrl + (long)m*KE;
  for(int i=threadIdx.x; i<KE; i+=256){ dsth[i] = smh[i]; dstl[i] = sml[i]; }
}

// ---------------- LayerNorm ----------------------------------------------------
__global__ void ln_k(const float* __restrict__ x, const float* __restrict__ gw,
                     const float* __restrict__ gb, float* __restrict__ o){
  int m = blockIdx.x;
  int tid = threadIdx.x;
  const float* xr = x + (long)m*DIM;
  float v[4]; float s = 0.f, sq = 0.f;
  #pragma unroll
  for(int j=0;j<4;j++){ float t = xr[tid + j*128]; v[j] = t; s += t; sq += t*t; }
  #pragma unroll
  for(int off=16; off; off>>=1){
    s  += __shfl_xor_sync(0xffffffffu, s,  off);
    sq += __shfl_xor_sync(0xffffffffu, sq, off);
  }
  __shared__ float ss[4], sqs[4];
  if((tid & 31) == 0){ ss[tid>>5] = s; sqs[tid>>5] = sq; }
  __syncthreads();
  s  = (ss[0]+ss[1]) + (ss[2]+ss[3]);
  sq = (sqs[0]+sqs[1]) + (sqs[2]+sqs[3]);
  float mean = s * (1.f/DIM);
  float var  = sq * (1.f/DIM) - mean*mean;
  float rstd = rsqrtf(var + 1e-5f);
  float* orow = o + (long)m*DIM;
  #pragma unroll
  for(int j=0;j<4;j++){
    int d = tid + j*128;
    orow[d] = (v[j] - mean)*rstd*gw[d] + gb[d];
  }
}

// ---------------- time-shift mixes ---------------------------------------------
__global__ void mix3_k(const float* __restrict__ xn, const float* __restrict__ mk,
                       const float* __restrict__ mv, const float* __restrict__ mr){
  int g = blockIdx.x*256 + threadIdx.x;
  int t = g*2;
  int d = t & (DIM-1);
  int tok = (t >> 9) & (USEQ-1);
  float2 cur = *(const float2*)&xn[t];
  float2 sh = tok ? *(const float2*)&xn[t - DIM] : make_float2(0.f, 0.f);
  float d0 = cur.x - sh.x, d1 = cur.y - sh.y;
  uint32_t h, l;
  split2(fmaf(d0, mk[d], sh.x), fmaf(d1, mk[d+1], sh.y), h, l);
  *(uint32_t*)&g_xkh[t] = h; *(uint32_t*)&g_xkl[t] = l;
  split2(fmaf(d0, mv[d], sh.x), fmaf(d1, mv[d+1], sh.y), h, l);
  *(uint32_t*)&g_xvh[t] = h; *(uint32_t*)&g_xvl[t] = l;
  split2(fmaf(d0, mr[d], sh.x), fmaf(d1, mr[d+1], sh.y), h, l);
  *(uint32_t*)&g_xrh[t] = h; *(uint32_t*)&g_xrl[t] = l;
}
__global__ void mix2_k(const float* __restrict__ xn, const float* __restrict__ mk,
                       const float* __restrict__ mr){
  int g = blockIdx.x*256 + threadIdx.x;
  int t = g*2;
  int d = t & (DIM-1);
  int tok = (t >> 9) & (USEQ-1);
  float2 cur = *(const float2*)&xn[t];
  float2 sh = tok ? *(const float2*)&xn[t - DIM] : make_float2(0.f, 0.f);
  float d0 = cur.x - sh.x, d1 = cur.y - sh.y;
  uint32_t h, l;
  split2(fmaf(d0, mk[d], sh.x), fmaf(d1, mk[d+1], sh.y), h, l);
  *(uint32_t*)&g_xkh[t] = h; *(uint32_t*)&g_xkl[t] = l;
  split2(fmaf(d0, mr[d], sh.x), fmaf(d1, mr[d+1], sh.y), h, l);
  *(uint32_t*)&g_xrh[t] = h; *(uint32_t*)&g_xrl[t] = l;
}

// ---------------- WKV scan, pipelined, bf16 split output -----------------------
#define WG 8
__device__ __forceinline__ void wkv_load(const float* kp, const float* vp,
                                         const float* rp, long off0,
                                         float* kb, float* vb, float* rb){
  #pragma unroll
  for(int j=0;j<WG;j++){
    long off = off0 + (long)j*DIM;
    kb[j] = __ldg(kp + off); vb[j] = __ldg(vp + off); rb[j] = __ldg(rp + off);
  }
}
__device__ __forceinline__ void wkv_step(float* kb, float* vb, float* rb,
                                         bf* oh, bf* ol, long off0,
                                         float w, float u,
                                         float& aa, float& bb, float& pp){
  #pragma unroll
  for(int j=0;j<WG;j++){
    float kt = kb[j], vt = vb[j];
    float ww = u + kt;
    float p  = fmaxf(pp, ww);
    float e1 = __expf(pp - p), e2 = __expf(ww - p);
    float o  = rb[j] * (e1*aa + e2*vt) / (e1*bb + e2);
    bf h = __float2bfloat16(o);
    long off = off0 + (long)j*DIM;
    oh[off] = h;
    ol[off] = __float2bfloat16(o - __bfloat162float(h));
    float ww2 = pp + w;
    float p2  = fmaxf(ww2, kt);
    e1 = __expf(ww2 - p2); e2 = __expf(kt - p2);
    aa = e1*aa + e2*vt; bb = e1*bb + e2; pp = p2;
  }
}
__global__ void wkv_k(const float* __restrict__ k, const float* __restrict__ v,
                      const float* __restrict__ r,
                      const float* __restrict__ dec, const float* __restrict__ fir){
  int t = blockIdx.x*blockDim.x + threadIdx.x;
  int d = t & (DIM-1); int b = t >> 9;
  float w = -__expf(dec[d]);
  float u = fir[d];
  float aa = 0.f, bb = 0.f, pp = -1e38f;
  long base = (long)b*USEQ*DIM + d;
  const float* kp = k + base;
  const float* vp = v + base;
  const float* rp = r + base;
  bf* oh = g_rwh + base;
  bf* ol = g_rwl + base;
  const int NG = USEQ/WG;
  float k0b[WG], v0b[WG], r0b[WG];
  float k1b[WG], v1b[WG], r1b[WG];
  wkv_load(kp, vp, rp, 0, k0b, v0b, r0b);
  for(int g=0; g<NG; g+=2){
    long off1 = (long)(g+1)*WG*DIM;
    wkv_load(kp, vp, rp, off1, k1b, v1b, r1b);
    wkv_step(k0b, v0b, r0b, oh, ol, (long)g*WG*DIM, w, u, aa, bb, pp);
    if(g+2 < NG){
      long off2 = (long)(g+2)*WG*DIM;
      wkv_load(kp, vp, rp, off2, k0b, v0b, r0b);
    }
    wkv_step(k1b, v1b, r1b, oh, ol, off1, w, u, aa, bb, pp);
  }
}

// ---------------- olens tail ----------------------------------------------------
__global__ void tail_k(const int* __restrict__ x_len, float* __restrict__ out, int out_size){
  int b = threadIdx.x;
  if(b < BATCH && out_size >= HTOK + BATCH){
    int l1 = (x_len[b] - 1)/2 + 1;
    int ol = (l1 - 1)/2 + 1;
    out[HTOK + b] = (float)ol;
  }
}

// ---------------- host side -----------------------------------------------------
template <typename T>
static void* symaddr(const T& s){ void* p = nullptr; cudaGetSymbolAddress(&p, s); return p; }

template<int ACT, int EPI, int OUT>
static void gemm(int M, int N, int K, const bf* Ah, const bf* Al,
                 const bf* Bh, const bf* Bl, const float* bias,
                 float* C, bf* Ch, bf* Cl, const float* mul){
  cudaFuncSetAttribute(mgemm_k<ACT,EPI,OUT>, cudaFuncAttributeMaxDynamicSharedMemorySize, MSMEM);
  dim3 grid(N/256, M/128);
  mgemm_k<ACT,EPI,OUT><<<grid, 256, MSMEM>>>(M, N, K, Ah, Al, Bh, Bl, bias, C, Ch, Cl, mul);
}

extern "C" void kernel_launch(void* const* d_in, const int* in_sizes, int n_in,
                              void* d_out, int out_size){
  const float* x       = (const float*)d_in[0];
  const int*   x_len   = (const int*)  d_in[1];
  const float* conv1_w = (const float*)d_in[2];
  const float* conv1_b = (const float*)d_in[3];
  const float* conv2_w = (const float*)d_in[4];
  const float* conv2_b = (const float*)d_in[5];
  const float* conv3_w = (const float*)d_in[6];
  const float* conv3_b = (const float*)d_in[7];
  const float* embed_w = (const float*)d_in[8];
  const float* embed_b = (const float*)d_in[9];
  const float* eln_g   = (const float*)d_in[10];
  const float* eln_b   = (const float*)d_in[11];
  const float* lag     = (const float*)d_in[12];
  const float* lab     = (const float*)d_in[13];
  const float* dec     = (const float*)d_in[14];
  const float* fir     = (const float*)d_in[15];
  const float* amk     = (const float*)d_in[16];
  const float* amv     = (const float*)d_in[17];
  const float* amr     = (const float*)d_in[18];
  const float* awk     = (const float*)d_in[19];
  const float* awv     = (const float*)d_in[20];
  const float* awr     = (const float*)d_in[21];
  const float* awo     = (const float*)d_in[22];
  const float* lfg     = (const float*)d_in[23];
  const float* lfb     = (const float*)d_in[24];
  const float* fmk     = (const float*)d_in[25];
  const float* fmr     = (const float*)d_in[26];
  const float* fwk     = (const float*)d_in[27];
  const float* fwv     = (const float*)d_in[28];
  const float* fwr     = (const float*)d_in[29];
  const float* flg     = (const float*)d_in[30];
  const float* flb     = (const float*)d_in[31];
  float* out = (float*)d_out;

  bf* p_col2h = (bf*)symaddr(g_col2h); bf* p_col2l = (bf*)symaddr(g_col2l);
  bf* p_c2h   = (bf*)symaddr(g_c2h);   bf* p_c2l   = (bf*)symaddr(g_c2l);
  bf* p_col3h = (bf*)symaddr(g_col3h); bf* p_col3l = (bf*)symaddr(g_col3l);
  bf* p_c3h   = (bf*)symaddr(g_c3h);   bf* p_c3l   = (bf*)symaddr(g_c3l);
  bf* p_yrh   = (bf*)symaddr(g_yrh);   bf* p_yrl   = (bf*)symaddr(g_yrl);
  float* p_t0 = (float*)symaddr(g_t0);
  float* p_h  = (float*)symaddr(g_h);
  float* p_xn = (float*)symaddr(g_xn);
  bf* p_xkh = (bf*)symaddr(g_xkh); bf* p_xkl = (bf*)symaddr(g_xkl);
  bf* p_xvh = (bf*)symaddr(g_xvh); bf* p_xvl = (bf*)symaddr(g_xvl);
  bf* p_xrh = (bf*)symaddr(g_xrh); bf* p_xrl = (bf*)symaddr(g_xrl);
  float* p_k = (float*)symaddr(g_k);
  float* p_v = (float*)symaddr(g_v);
  float* p_r = (float*)symaddr(g_r);
  bf* p_rwh = (bf*)symaddr(g_rwh); bf* p_rwl = (bf*)symaddr(g_rwl);
  bf* p_kkh = (bf*)symaddr(g_kkh); bf* p_kkl = (bf*)symaddr(g_kkl);
  bf* p_w2Th = (bf*)symaddr(g_w2Th); bf* p_w2Tl = (bf*)symaddr(g_w2Tl);
  bf* p_w3Th = (bf*)symaddr(g_w3Th); bf* p_w3Tl = (bf*)symaddr(g_w3Tl);
  bf* p_ewTh = (bf*)symaddr(g_ewTh); bf* p_ewTl = (bf*)symaddr(g_ewTl);
  bf* p_aqkvTh = (bf*)symaddr(g_aqkvTh); bf* p_aqkvTl = (bf*)symaddr(g_aqkvTl);
  bf* p_awoTh  = (bf*)symaddr(g_awoTh);  bf* p_awoTl  = (bf*)symaddr(g_awoTl);
  bf* p_fkrTh  = (bf*)symaddr(g_fkrTh);  bf* p_fkrTl  = (bf*)symaddr(g_fkrTl);
  bf* p_fwvTh  = (bf*)symaddr(g_fwvTh);  bf* p_fwvTl  = (bf*)symaddr(g_fwvTl);

  // launches 1-6 (launch 6 = conv3 GEMM profiled by ncu -s 5 -c 1)
  prep_conv_k<<<(C2*K2C + C3*K3C + 255)/256, 256>>>(conv2_w, conv3_w);
  conv1_k<<<(BATCH*H1*W1*C1)/256, 256>>>(x, conv1_w, conv1_b);
  im2col2_k<<<(MCONV*(K2C/4))/256, 256>>>();
  gemm<1,0,1>(MCONV, C2, K2C, p_col2h, p_col2l, p_w2Th, p_w2Tl, conv2_b,
              nullptr, p_c2h, p_c2l, nullptr);
  im2col3_k<<<(MCONV*(K3C/4))/256, 256>>>();
  gemm<1,0,1>(MCONV, C3, K3C, p_col3h, p_col3l, p_w3Th, p_w3Tl, conv3_b,
              nullptr, p_c3h, p_c3l, nullptr);

  prep_big_k<<<18432, dim3(32,8)>>>(embed_w, awk, awv, awr, awo, fwr, fwk, fwv);
  reshape_k<<<MT, 256>>>();
  gemm<0,0,0>(MT, DIM, KE, p_yrh, p_yrl, p_ewTh, p_ewTl, embed_b,
              p_t0, nullptr, nullptr, nullptr);
  ln_k<<<MT, 128>>>(p_t0, eln_g, eln_b, p_h);

  // ---- RWKV blocks ----
  for(int i = 0; i < NB_; i++){
    long w2 = (long)i*DIM*DIM;
    long wh = (long)i*DIM*HID;
    long qb = (long)i*3*DIM*DIM;
    long fb = (long)i*(HID+DIM)*DIM;
    // time mixing
    ln_k<<<MT, 128>>>(p_h, lag + i*DIM, lab + i*DIM, p_xn);
    mix3_k<<<HTOK/512, 256>>>(p_xn, amk + i*DIM, amv + i*DIM, amr + i*DIM);
    gemm<0,0,0>(MT, DIM, DIM, p_xkh, p_xkl, p_aqkvTh + qb, p_aqkvTl + qb, nullptr,
                p_k, nullptr, nullptr, nullptr);
    gemm<0,0,0>(MT, DIM, DIM, p_xvh, p_xvl, p_aqkvTh + qb + (long)DIM*DIM,
                p_aqkvTl + qb + (long)DIM*DIM, nullptr,
                p_v, nullptr, nullptr, nullptr);
    gemm<2,0,0>(MT, DIM, DIM, p_xrh, p_xrl, p_aqkvTh + qb + 2L*DIM*DIM,
                p_aqkvTl + qb + 2L*DIM*DIM, nullptr,
                p_r, nullptr, nullptr, nullptr);
    wkv_k<<<(BATCH*DIM)/32, 32>>>(p_k, p_v, p_r, dec + i*DIM, fir + i*DIM);
    gemm<0,1,0>(MT, DIM, DIM, p_rwh, p_rwl, p_awoTh + w2, p_awoTl + w2, nullptr,
                p_h, nullptr, nullptr, nullptr);
    // channel mixing
    ln_k<<<MT, 128>>>(p_h, lfg + i*DIM, lfb + i*DIM, p_xn);
    mix2_k<<<HTOK/512, 256>>>(p_xn, fmk + i*DIM, fmr + i*DIM);
    gemm<3,0,1>(MT, HID, DIM, p_xkh, p_xkl, p_fkrTh + fb, p_fkrTl + fb, nullptr,
                nullptr, p_kkh, p_kkl, nullptr);
    gemm<2,0,0>(MT, DIM, DIM, p_xrh, p_xrl, p_fkrTh + fb + (long)HID*DIM,
                p_fkrTl + fb + (long)HID*DIM, nullptr,
                p_r, nullptr, nullptr, nullptr);
    gemm<0,2,0>(MT, DIM, HID, p_kkh, p_kkl, p_fwvTh + wh, p_fwvTl + wh, nullptr,
                p_h, nullptr, nullptr, p_r);
  }

  ln_k<<<MT, 128>>>(p_h, flg, flb, out);
  tail_k<<<1, 32>>>(x_len, out, out_size);
}

// round 11
// speedup vs baseline: 1.3110x; 1.0081x over previous
#include <cuda_runtime.h>
#include <cuda_bf16.h>
#include <cstdint>

typedef __nv_bfloat16 bf;

#define NB_   4
#define BATCH 8
#define LEN   4096
#define FREQ  80
#define DIM   512
#define HID   2048
#define USEQ  1024
#define C1    128
#define C2    256
#define C3    512
#define H1    2048
#define W1    40
#define H2    1024
#define W2    20
#define MCONV (BATCH*H2*W2)      /* 163840 */
#define K2C   (9*C1)             /* 1152 */
#define K3C   (9*C2)             /* 2304 */
#define KE    (C3*W2)            /* 10240 */
#define MT    (BATCH*USEQ)       /* 8192 */
#define HTOK  (MT*DIM)           /* 4194304 */

// ---------------- scratch (device globals; no allocations) ----------------
__device__ float g_conv1[BATCH*H1*W1*C1];
__device__ bf g_col2h[MCONV*K2C],  g_col2l[MCONV*K2C];
__device__ bf g_c2h[MCONV*C2],     g_c2l[MCONV*C2];
__device__ bf g_col3h[MCONV*K3C],  g_col3l[MCONV*K3C];
__device__ bf g_c3h[MCONV*C3],     g_c3l[MCONV*C3];
__device__ bf g_yrh[MT*KE],        g_yrl[MT*KE];
__device__ float g_t0[HTOK];
__device__ float g_h[HTOK];
__device__ float g_xn[HTOK];
__device__ bf g_xkh[HTOK], g_xkl[HTOK];
__device__ bf g_xvh[HTOK], g_xvl[HTOK];
__device__ bf g_xrh[HTOK], g_xrl[HTOK];
__device__ float g_k[HTOK];
__device__ float g_v[HTOK];
__device__ float g_r[HTOK];
__device__ bf g_rwh[HTOK], g_rwl[HTOK];
__device__ bf g_kkh[MT*HID], g_kkl[MT*HID];
// transposed+split weights, [N][K] K-major bf16 hi/lo
__device__ bf g_w2Th[C2*K2C],  g_w2Tl[C2*K2C];
__device__ bf g_w3Th[C3*K3C],  g_w3Tl[C3*K3C];
__device__ bf g_ewTh[DIM*KE],  g_ewTl[DIM*KE];
__device__ bf g_aqkvTh[NB_*3*DIM*DIM], g_aqkvTl[NB_*3*DIM*DIM];
__device__ bf g_awoTh[NB_*DIM*DIM],    g_awoTl[NB_*DIM*DIM];
__device__ bf g_fkrTh[NB_*(HID+DIM)*DIM], g_fkrTl[NB_*(HID+DIM)*DIM];
__device__ bf g_fwvTh[NB_*DIM*HID],    g_fwvTl[NB_*DIM*HID];

// ================== helpers ==================
__device__ __forceinline__ uint32_t smem_to_u32(const void* p) {
  uint32_t a;
  asm("{ .reg .u64 t; cvta.to.shared.u64 t, %1; cvt.u32.u64 %0, t; }"
      : "=r"(a) : "l"(p));
  return a;
}
__device__ __forceinline__ void ldsm4(uint32_t* r, uint32_t addr){
  asm volatile("ldmatrix.sync.aligned.m8n8.x4.shared.b16 {%0,%1,%2,%3}, [%4];"
    : "=r"(r[0]),"=r"(r[1]),"=r"(r[2]),"=r"(r[3]) : "r"(addr));
}
__device__ __forceinline__ void mma_bf16(float* d, const uint32_t* a, const uint32_t* b){
  asm volatile("mma.sync.aligned.m16n8k16.row.col.f32.bf16.bf16.f32 "
    "{%0,%1,%2,%3}, {%4,%5,%6,%7}, {%8,%9}, {%0,%1,%2,%3};"
    : "+f"(d[0]),"+f"(d[1]),"+f"(d[2]),"+f"(d[3])
    : "r"(a[0]),"r"(a[1]),"r"(a[2]),"r"(a[3]), "r"(b[0]),"r"(b[1]));
}
__device__ __forceinline__ void cp16(uint32_t s, const void* g){
  asm volatile("cp.async.cg.shared.global [%0], [%1], 16;" :: "r"(s), "l"(g));
}
#define CP_COMMIT() asm volatile("cp.async.commit_group;" ::: "memory")
#define CP_WAIT1()  asm volatile("cp.async.wait_group 1;" ::: "memory")

__device__ __forceinline__ void split2(float v0, float v1, uint32_t& h, uint32_t& l){
  __nv_bfloat162 hh = __floats2bfloat162_rn(v0, v1);
  float r0 = v0 - __bfloat162float(hh.x);
  float r1 = v1 - __bfloat162float(hh.y);
  __nv_bfloat162 ll = __floats2bfloat162_rn(r0, r1);
  h = *(uint32_t*)&hh; l = *(uint32_t*)&ll;
}
__device__ __forceinline__ void split4(float4 v, uint2& hi, uint2& lo){
  split2(v.x, v.y, hi.x, lo.x);
  split2(v.z, v.w, hi.y, lo.y);
}
__device__ __forceinline__ float sgm(float v){ return 1.f/(1.f + __expf(-v)); }

// ====== bf16x3 MMA GEMM: CTA 128x256, Kchunk=32, 8 warps (64x64 tiles) =======
// 3-stage cp.async pipeline, register-lean flat loader.
// ACT: 0 none,1 relu,2 sigmoid,3 relu^2 ; EPI: 0 store,1 +=,2 C+mul*acc
// OUT: 0 fp32 C ; 1 bf16 split Ch/Cl
#define PITCH 40
#define AHI_O 0
#define ALO_O 10240
#define BHI_O 20480
#define BLO_O 40960
#define STG_B 61440
#define MSMEM (3*STG_B)

template<int ACT, int EPI, int OUT>
__global__ void __launch_bounds__(256, 1) mgemm_k(int M, int N, int K,
    const bf* __restrict__ Ah, const bf* __restrict__ Al,
    const bf* __restrict__ Bh, const bf* __restrict__ Bl,
    const float* __restrict__ bias, float* __restrict__ C,
    bf* __restrict__ Ch, bf* __restrict__ Cl, const float* __restrict__ mul){
  extern __shared__ char smarr[];
  uint32_t smb = smem_to_u32(smarr);
  int tid = threadIdx.x, lane = tid & 31, wid = tid >> 5;
  int wm = wid >> 2, wn = wid & 3;          // warp grid 2(m) x 4(n), tiles 64x64
  long m0 = (long)blockIdx.y * 128;
  int  n0 = blockIdx.x * 256;

  // register-lean loader: region is compile-time per unroll slot,
  // row = (tid>>2) + j*64, col-segment w = (tid&3).
  const bf* Ahb = Ah + m0*(long)K;
  const bf* Alb = Al + m0*(long)K;
  const bf* Bhb = Bh + (long)n0*K;
  const bf* Blb = Bl + (long)n0*K;
  long lg = (long)(tid >> 2)*K + (tid & 3)*8;   // within-region global elem offset
  uint32_t ls = (uint32_t)(tid >> 2)*80 + (tid & 3)*16;  // within-region smem offset
  long K64 = (long)K*64;

  // ldmatrix per-lane byte offsets (within hi arrays; lo at +delta)
  uint32_t aoff = (((uint32_t)wm*64 + ((lane>>3)&1)*8 + (lane&7))*PITCH + ((lane>>4)&1)*8) * 2;
  uint32_t boff = (((uint32_t)wn*64 + ((lane>>4)&1)*8 + (lane&7))*PITCH + ((lane>>3)&1)*8) * 2;

  float acc[4][8][4];
  #pragma unroll
  for(int i=0;i<4;i++)
    #pragma unroll
    for(int j=0;j<8;j++)
      #pragma unroll
      for(int q=0;q<4;q++) acc[i][j][q] = 0.f;

  int nc = K >> 5;

  #define LOAD_CHUNK(c, sidx) do { \
    uint32_t stg_ = smb + (sidx)*STG_B; \
    long go_ = lg + (long)(c)*32; \
    cp16(stg_ + AHI_O + ls,         Ahb + go_); \
    cp16(stg_ + AHI_O + ls + 5120,  Ahb + go_ + K64); \
    cp16(stg_ + ALO_O + ls,         Alb + go_); \
    cp16(stg_ + ALO_O + ls + 5120,  Alb + go_ + K64); \
    cp16(stg_ + BHI_O + ls,         Bhb + go_); \
    cp16(stg_ + BHI_O + ls + 5120,  Bhb + go_ + K64); \
    cp16(stg_ + BHI_O + ls + 10240, Bhb + go_ + 2*K64); \
    cp16(stg_ + BHI_O + ls + 15360, Bhb + go_ + 3*K64); \
    cp16(stg_ + BLO_O + ls,         Blb + go_); \
    cp16(stg_ + BLO_O + ls + 5120,  Blb + go_ + K64); \
    cp16(stg_ + BLO_O + ls + 10240, Blb + go_ + 2*K64); \
    cp16(stg_ + BLO_O + ls + 15360, Blb + go_ + 3*K64); \
  } while(0)

  LOAD_CHUNK(0, 0); CP_COMMIT();
  LOAD_CHUNK(1, 1); CP_COMMIT();

  for(int c = 0; c < nc; c++){
    CP_WAIT1();
    __syncthreads();
    if(c + 2 < nc){ LOAD_CHUNK(c + 2, (c + 2) % 3); }
    CP_COMMIT();
    uint32_t stg = smb + (c % 3)*STG_B;
    #pragma unroll
    for(int ks = 0; ks < 2; ks++){
      uint32_t ahk[4][4], alk[4][4], bhk[4][4], blk[4][4];
      #pragma unroll
      for(int mt = 0; mt < 4; mt++){
        uint32_t ad = stg + AHI_O + aoff + mt*(16*PITCH*2) + ks*32;
        ldsm4(ahk[mt], ad);
        ldsm4(alk[mt], ad + (ALO_O - AHI_O));
      }
      #pragma unroll
      for(int ng = 0; ng < 4; ng++){
        uint32_t bd = stg + BHI_O + boff + ng*(16*PITCH*2) + ks*32;
        ldsm4(bhk[ng], bd);
        ldsm4(blk[ng], bd + (BLO_O - BHI_O));
      }
      #pragma unroll
      for(int mt = 0; mt < 4; mt++)
        #pragma unroll
        for(int nt = 0; nt < 8; nt++)
          mma_bf16(acc[mt][nt], ahk[mt], &bhk[nt>>1][(nt&1)*2]);
      #pragma unroll
      for(int mt = 0; mt < 4; mt++)
        #pragma unroll
        for(int nt = 0; nt < 8; nt++)
          mma_bf16(acc[mt][nt], ahk[mt], &blk[nt>>1][(nt&1)*2]);
      #pragma unroll
      for(int mt = 0; mt < 4; mt++)
        #pragma unroll
        for(int nt = 0; nt < 8; nt++)
          mma_bf16(acc[mt][nt], alk[mt], &bhk[nt>>1][(nt&1)*2]);
    }
  }

  // ---- epilogue ----
  int mrow = lane >> 2;
  int ncol = (lane & 3) * 2;
  #pragma unroll
  for(int mt = 0; mt < 4; mt++){
    #pragma unroll
    for(int nt = 0; nt < 8; nt++){
      #pragma unroll
      for(int hf = 0; hf < 2; hf++){
        long gm = m0 + wm*64 + mt*16 + mrow + hf*8;
        int  gn = n0 + wn*64 + nt*8 + ncol;
        float v0 = acc[mt][nt][hf*2+0];
        float v1 = acc[mt][nt][hf*2+1];
        if(bias){ v0 += bias[gn]; v1 += bias[gn+1]; }
        if(ACT == 1){ v0 = fmaxf(v0,0.f); v1 = fmaxf(v1,0.f); }
        else if(ACT == 2){ v0 = sgm(v0); v1 = sgm(v1); }
        else if(ACT == 3){ v0 = fmaxf(v0,0.f); v0 *= v0; v1 = fmaxf(v1,0.f); v1 *= v1; }
        if(OUT == 0){
          float* cp = C + gm*N + gn;
          if(EPI == 1){ v0 += cp[0]; v1 += cp[1]; }
          else if(EPI == 2){
            const float* mp = mul + gm*N + gn;
            v0 = cp[0] + mp[0]*v0; v1 = cp[1] + mp[1]*v1;
          }
          *(float2*)cp = make_float2(v0, v1);
        } else {
          uint32_t hh, ll;
          split2(v0, v1, hh, ll);
          *(uint32_t*)&Ch[gm*N + gn] = hh;
          *(uint32_t*)&Cl[gm*N + gn] = ll;
        }
      }
    }
  }
}

// ---------------- conv1 ------------------------------------------------------
__global__ void conv1_k(const float* __restrict__ x, const float* __restrict__ w,
                        const float* __restrict__ bias){
  int t = blockIdx.x*256 + threadIdx.x;
  int co = t & 127;
  int rest = t >> 7;
  int wo = rest % W1; rest /= W1;
  int ho = rest % H1; int b = rest / H1;
  float acc = bias[co];
  int hi0 = 2*ho - 1, wi0 = 2*wo - 1;
  #pragma unroll
  for(int kh=0; kh<3; kh++){
    int hi = hi0 + kh;
    if(hi < 0 || hi >= LEN) continue;
    #pragma unroll
    for(int kw=0; kw<3; kw++){
      int wi = wi0 + kw;
      if(wi < 0 || wi >= FREQ) continue;
      acc = fmaf(x[(hi + (long)b*LEN)*FREQ + wi], w[co*9 + kh*3 + kw], acc);
    }
  }
  g_conv1[t] = fmaxf(acc, 0.f);
}

// ---------------- conv weight prep -------------------------------------------
__global__ void prep_conv_k(const float* __restrict__ w2, const float* __restrict__ w3){
  int t = blockIdx.x*256 + threadIdx.x;
  if(t < C2*K2C){
    int co = t / K2C; int idx = t % K2C;
    int r = idx / C1; int ci = idx % C1;
    float v = w2[co*(C1*9) + ci*9 + r];
    bf h = __float2bfloat16(v);
    g_w2Th[t] = h; g_w2Tl[t] = __float2bfloat16(v - __bfloat162float(h));
  } else {
    int u = t - C2*K2C;
    if(u >= C3*K3C) return;
    int co = u / K3C; int idx = u % K3C;
    int r = idx / C2; int ci = idx % C2;
    float v = w3[co*(C2*9) + ci*9 + r];
    bf h = __float2bfloat16(v);
    g_w3Th[u] = h; g_w3Tl[u] = __float2bfloat16(v - __bfloat162float(h));
  }
}

// ------ big weight prep: transpose [R][C]->[C][R] + split + concat -----------
__global__ void prep_big_k(const float* __restrict__ embed_w,
                           const float* __restrict__ awk, const float* __restrict__ awv,
                           const float* __restrict__ awr, const float* __restrict__ awo,
                           const float* __restrict__ fwr, const float* __restrict__ fwk,
                           const float* __restrict__ fwv){
  int t = blockIdx.x;
  const float* in; bf *oh, *ol; int R, C, tr, tc;
  if(t < 5120){
    in = embed_w; oh = g_ewTh; ol = g_ewTl; R = KE; C = DIM;
    tr = t / 16; tc = t % 16;
  } else {
    int u = t - 5120;
    int i = u / 3328; int v = u % 3328;
    long o2 = (long)i*DIM*DIM, oh2 = (long)i*DIM*HID;
    long qb = (long)i*3*DIM*DIM, fb = (long)i*(HID+DIM)*DIM;
    if(v < 768){
      int kind = v / 256; int vv = v % 256;
      R = DIM; C = DIM; tr = vv / 16; tc = vv % 16;
      in = (kind == 0 ? awk : kind == 1 ? awv : awr) + o2;
      oh = g_aqkvTh + qb + (long)kind*DIM*DIM;
      ol = g_aqkvTl + qb + (long)kind*DIM*DIM;
    } else if(v < 1024){
      int vv = v - 768;
      R = DIM; C = DIM; tr = vv / 16; tc = vv % 16;
      in = awo + o2; oh = g_awoTh + o2; ol = g_awoTl + o2;
    } else if(v < 2048){
      int vv = v - 1024;
      R = DIM; C = HID; tr = vv / 64; tc = vv % 64;
      in = fwk + oh2; oh = g_fkrTh + fb; ol = g_fkrTl + fb;
    } else if(v < 2304){
      int vv = v - 2048;
      R = DIM; C = DIM; tr = vv / 16; tc = vv % 16;
      in = fwr + o2;
      oh = g_fkrTh + fb + (long)HID*DIM;
      ol = g_fkrTl + fb + (long)HID*DIM;
    } else {
      int vv = v - 2304;
      R = HID; C = DIM; tr = vv / 16; tc = vv % 16;
      in = fwv + oh2; oh = g_fwvTh + oh2; ol = g_fwvTl + oh2;
    }
  }
  __shared__ float tile[32][33];
  int r0 = tr*32, c0 = tc*32;
  int x = c0 + threadIdx.x;
  for(int dy = threadIdx.y; dy < 32; dy += 8)
    tile[dy][threadIdx.x] = in[(long)(r0 + dy)*C + x];
  __syncthreads();
  int xo = r0 + threadIdx.x;
  for(int dy = threadIdx.y; dy < 32; dy += 8){
    float v = tile[threadIdx.x][dy];
    bf h = __float2bfloat16(v);
    long oidx = (long)(c0 + dy)*R + xo;
    oh[oidx] = h; ol[oidx] = __float2bfloat16(v - __bfloat162float(h));
  }
}

// ---------------- im2col, split output ---------------------------------------
__global__ void im2col2_k(){
  int t = blockIdx.x*256 + threadIdx.x;
  int k4 = t % (K2C/4); int m = t / (K2C/4);
  int k = k4*4;
  int r = k >> 7; int ci = k & 127;
  int kh = r / 3, kw = r % 3;
  int wo = m % W2; int rest = m / W2;
  int ho = rest % H2; int b = rest / H2;
  int hi = 2*ho + kh - 1, wi = 2*wo + kw - 1;
  float4 v = make_float4(0.f,0.f,0.f,0.f);
  if(hi >= 0 && hi < H1 && wi >= 0 && wi < W1)
    v = *(const float4*)&g_conv1[((b*H1 + hi)*W1 + wi)*C1 + ci];
  uint2 hh, ll;
  split4(v, hh, ll);
  long dst = (long)m*K2C + k;
  *(uint2*)&g_col2h[dst] = hh;
  *(uint2*)&g_col2l[dst] = ll;
}
__global__ void im2col3_k(){
  int t = blockIdx.x*256 + threadIdx.x;
  int k4 = t % (K3C/4); int m = t / (K3C/4);
  int k = k4*4;
  int r = k >> 8; int ci = k & 255;
  int kh = r / 3, kw = r % 3;
  int wo = m % W2; int rest = m / W2;
  int ho = rest % H2; int b = rest / H2;
  int hi = ho + kh - 1, wi = wo + kw - 1;
  uint2 vh = make_uint2(0,0), vl = make_uint2(0,0);
  if(hi >= 0 && hi < H2 && wi >= 0 && wi < W2){
    long src = (long)((b*H2 + hi)*W2 + wi)*C2 + ci;
    vh = *(const uint2*)&g_c2h[src];
    vl = *(const uint2*)&g_c2l[src];
  }
  long dst = (long)m*K3C + k;
  *(uint2*)&g_col3h[dst] = vh;
  *(uint2*)&g_col3l[dst] = vl;
}

// ---------------- reshape ------------------------------------------------------
__global__ void reshape_k(){
  __shared__ uint16_t smh[KE], sml[KE];
  int m = blockIdx.x;
  const uint16_t* srch = (const uint16_t*)g_c3h + (long)m*KE;
  const uint16_t* srcl = (const uint16_t*)g_c3l + (long)m*KE;
  for(int i=threadIdx.x; i<KE; i+=256){
    int w = i / 512, c = i & 511;
    int d = c*W2 + w;
    smh[d] = srch[i];
    sml[d] = srcl[i];
  }
  __syncthreads();
  uint16_t* dsth = (uint16_t*)g_yrh + (long)m*KE;
  uint16_t* dstl = (uint16_t*)g_yrl + (long)m*KE;
  for(int i=threadIdx.x; i<KE; i+=256){ dsth[i] = smh[i]; dstl[i] = sml[i]; }
}

// ---------------- LayerNorm ----------------------------------------------------
__global__ void ln_k(const float* __restrict__ x, const float* __restrict__ gw,
                     const float* __restrict__ gb, float* __restrict__ o){
  int m = blockIdx.x;
  int tid = threadIdx.x;
  const float* xr = x + (long)m*DIM;
  float v[4]; float s = 0.f, sq = 0.f;
  #pragma unroll
  for(int j=0;j<4;j++){ float t = xr[tid + j*128]; v[j] = t; s += t; sq += t*t; }
  #pragma unroll
  for(int off=16; off; off>>=1){
    s  += __shfl_xor_sync(0xffffffffu, s,  off);
    sq += __shfl_xor_sync(0xffffffffu, sq, off);
  }
  __shared__ float ss[4], sqs[4];
  if((tid & 31) == 0){ ss[tid>>5] = s; sqs[tid>>5] = sq; }
  __syncthreads();
  s  = (ss[0]+ss[1]) + (ss[2]+ss[3]);
  sq = (sqs[0]+sqs[1]) + (sqs[2]+sqs[3]);
  float mean = s * (1.f/DIM);
  float var  = sq * (1.f/DIM) - mean*mean;
  float rstd = rsqrtf(var + 1e-5f);
  float* orow = o + (long)m*DIM;
  #pragma unroll
  for(int j=0;j<4;j++){
    int d = tid + j*128;
    orow[d] = (v[j] - mean)*rstd*gw[d] + gb[d];
  }
}

// ---------------- time-shift mixes ---------------------------------------------
__global__ void mix3_k(const float* __restrict__ xn, const float* __restrict__ mk,
                       const float* __restrict__ mv, const float* __restrict__ mr){
  int g = blockIdx.x*256 + threadIdx.x;
  int t = g*2;
  int d = t & (DIM-1);
  int tok = (t >> 9) & (USEQ-1);
  float2 cur = *(const float2*)&xn[t];
  float2 sh = tok ? *(const float2*)&xn[t - DIM] : make_float2(0.f, 0.f);
  float d0 = cur.x - sh.x, d1 = cur.y - sh.y;
  uint32_t h, l;
  split2(fmaf(d0, mk[d], sh.x), fmaf(d1, mk[d+1], sh.y), h, l);
  *(uint32_t*)&g_xkh[t] = h; *(uint32_t*)&g_xkl[t] = l;
  split2(fmaf(d0, mv[d], sh.x), fmaf(d1, mv[d+1], sh.y), h, l);
  *(uint32_t*)&g_xvh[t] = h; *(uint32_t*)&g_xvl[t] = l;
  split2(fmaf(d0, mr[d], sh.x), fmaf(d1, mr[d+1], sh.y), h, l);
  *(uint32_t*)&g_xrh[t] = h; *(uint32_t*)&g_xrl[t] = l;
}
__global__ void mix2_k(const float* __restrict__ xn, const float* __restrict__ mk,
                       const float* __restrict__ mr){
  int g = blockIdx.x*256 + threadIdx.x;
  int t = g*2;
  int d = t & (DIM-1);
  int tok = (t >> 9) & (USEQ-1);
  float2 cur = *(const float2*)&xn[t];
  float2 sh = tok ? *(const float2*)&xn[t - DIM] : make_float2(0.f, 0.f);
  float d0 = cur.x - sh.x, d1 = cur.y - sh.y;
  uint32_t h, l;
  split2(fmaf(d0, mk[d], sh.x), fmaf(d1, mk[d+1], sh.y), h, l);
  *(uint32_t*)&g_xkh[t] = h; *(uint32_t*)&g_xkl[t] = l;
  split2(fmaf(d0, mr[d], sh.x), fmaf(d1, mr[d+1], sh.y), h, l);
  *(uint32_t*)&g_xrh[t] = h; *(uint32_t*)&g_xrl[t] = l;
}

// ---------------- WKV scan, pipelined, bf16 split output -----------------------
#define WG 8
__device__ __forceinline__ void wkv_load(const float* kp, const float* vp,
                                         const float* rp, long off0,
                                         float* kb, float* vb, float* rb){
  #pragma unroll
  for(int j=0;j<WG;j++){
    long off = off0 + (long)j*DIM;
    kb[j] = __ldg(kp + off); vb[j] = __ldg(vp + off); rb[j] = __ldg(rp + off);
  }
}
__device__ __forceinline__ void wkv_step(float* kb, float* vb, float* rb,
                                         bf* oh, bf* ol, long off0,
                                         float w, float u,
                                         float& aa, float& bb, float& pp){
  #pragma unroll
  for(int j=0;j<WG;j++){
    float kt = kb[j], vt = vb[j];
    float ww = u + kt;
    float p  = fmaxf(pp, ww);
    float e1 = __expf(pp - p), e2 = __expf(ww - p);
    float o  = rb[j] * (e1*aa + e2*vt) / (e1*bb + e2);
    bf h = __float2bfloat16(o);
    long off = off0 + (long)j*DIM;
    oh[off] = h;
    ol[off] = __float2bfloat16(o - __bfloat162float(h));
    float ww2 = pp + w;
    float p2  = fmaxf(ww2, kt);
    e1 = __expf(ww2 - p2); e2 = __expf(kt - p2);
    aa = e1*aa + e2*vt; bb = e1*bb + e2; pp = p2;
  }
}
__global__ void wkv_k(const float* __restrict__ k, const float* __restrict__ v,
                      const float* __restrict__ r,
                      const float* __restrict__ dec, const float* __restrict__ fir){
  int t = blockIdx.x*blockDim.x + threadIdx.x;
  int d = t & (DIM-1); int b = t >> 9;
  float w = -__expf(dec[d]);
  float u = fir[d];
  float aa = 0.f, bb = 0.f, pp = -1e38f;
  long base = (long)b*USEQ*DIM + d;
  const float* kp = k + base;
  const float* vp = v + base;
  const float* rp = r + base;
  bf* oh = g_rwh + base;
  bf* ol = g_rwl + base;
  const int NG = USEQ/WG;
  float k0b[WG], v0b[WG], r0b[WG];
  float k1b[WG], v1b[WG], r1b[WG];
  wkv_load(kp, vp, rp, 0, k0b, v0b, r0b);
  for(int g=0; g<NG; g+=2){
    long off1 = (long)(g+1)*WG*DIM;
    wkv_load(kp, vp, rp, off1, k1b, v1b, r1b);
    wkv_step(k0b, v0b, r0b, oh, ol, (long)g*WG*DIM, w, u, aa, bb, pp);
    if(g+2 < NG){
      long off2 = (long)(g+2)*WG*DIM;
      wkv_load(kp, vp, rp, off2, k0b, v0b, r0b);
    }
    wkv_step(k1b, v1b, r1b, oh, ol, off1, w, u, aa, bb, pp);
  }
}

// ---------------- olens tail ----------------------------------------------------
__global__ void tail_k(const int* __restrict__ x_len, float* __restrict__ out, int out_size){
  int b = threadIdx.x;
  if(b < BATCH && out_size >= HTOK + BATCH){
    int l1 = (x_len[b] - 1)/2 + 1;
    int ol = (l1 - 1)/2 + 1;
    out[HTOK + b] = (float)ol;
  }
}

// ---------------- host side -----------------------------------------------------
template <typename T>
static void* symaddr(const T& s){ void* p = nullptr; cudaGetSymbolAddress(&p, s); return p; }

template<int ACT, int EPI, int OUT>
static void gemm(int M, int N, int K, const bf* Ah, const bf* Al,
                 const bf* Bh, const bf* Bl, const float* bias,
                 float* C, bf* Ch, bf* Cl, const float* mul){
  cudaFuncSetAttribute(mgemm_k<ACT,EPI,OUT>, cudaFuncAttributeMaxDynamicSharedMemorySize, MSMEM);
  dim3 grid(N/256, M/128);
  mgemm_k<ACT,EPI,OUT><<<grid, 256, MSMEM>>>(M, N, K, Ah, Al, Bh, Bl, bias, C, Ch, Cl, mul);
}

extern "C" void kernel_launch(void* const* d_in, const int* in_sizes, int n_in,
                              void* d_out, int out_size){
  const float* x       = (const float*)d_in[0];
  const int*   x_len   = (const int*)  d_in[1];
  const float* conv1_w = (const float*)d_in[2];
  const float* conv1_b = (const float*)d_in[3];
  const float* conv2_w = (const float*)d_in[4];
  const float* conv2_b = (const float*)d_in[5];
  const float* conv3_w = (const float*)d_in[6];
  const float* conv3_b = (const float*)d_in[7];
  const float* embed_w = (const float*)d_in[8];
  const float* embed_b = (const float*)d_in[9];
  const float* eln_g   = (const float*)d_in[10];
  const float* eln_b   = (const float*)d_in[11];
  const float* lag     = (const float*)d_in[12];
  const float* lab     = (const float*)d_in[13];
  const float* dec     = (const float*)d_in[14];
  const float* fir     = (const float*)d_in[15];
  const float* amk     = (const float*)d_in[16];
  const float* amv     = (const float*)d_in[17];
  const float* amr     = (const float*)d_in[18];
  const float* awk     = (const float*)d_in[19];
  const float* awv     = (const float*)d_in[20];
  const float* awr     = (const float*)d_in[21];
  const float* awo     = (const float*)d_in[22];
  const float* lfg     = (const float*)d_in[23];
  const float* lfb     = (const float*)d_in[24];
  const float* fmk     = (const float*)d_in[25];
  const float* fmr     = (const float*)d_in[26];
  const float* fwk     = (const float*)d_in[27];
  const float* fwv     = (const float*)d_in[28];
  const float* fwr     = (const float*)d_in[29];
  const float* flg     = (const float*)d_in[30];
  const float* flb     = (const float*)d_in[31];
  float* out = (float*)d_out;

  bf* p_col2h = (bf*)symaddr(g_col2h); bf* p_col2l = (bf*)symaddr(g_col2l);
  bf* p_c2h   = (bf*)symaddr(g_c2h);   bf* p_c2l   = (bf*)symaddr(g_c2l);
  bf* p_col3h = (bf*)symaddr(g_col3h); bf* p_col3l = (bf*)symaddr(g_col3l);
  bf* p_c3h   = (bf*)symaddr(g_c3h);   bf* p_c3l   = (bf*)symaddr(g_c3l);
  bf* p_yrh   = (bf*)symaddr(g_yrh);   bf* p_yrl   = (bf*)symaddr(g_yrl);
  float* p_t0 = (float*)symaddr(g_t0);
  float* p_h  = (float*)symaddr(g_h);
  float* p_xn = (float*)symaddr(g_xn);
  bf* p_xkh = (bf*)symaddr(g_xkh); bf* p_xkl = (bf*)symaddr(g_xkl);
  bf* p_xvh = (bf*)symaddr(g_xvh); bf* p_xvl = (bf*)symaddr(g_xvl);
  bf* p_xrh = (bf*)symaddr(g_xrh); bf* p_xrl = (bf*)symaddr(g_xrl);
  float* p_k = (float*)symaddr(g_k);
  float* p_v = (float*)symaddr(g_v);
  float* p_r = (float*)symaddr(g_r);
  bf* p_rwh = (bf*)symaddr(g_rwh); bf* p_rwl = (bf*)symaddr(g_rwl);
  bf* p_kkh = (bf*)symaddr(g_kkh); bf* p_kkl = (bf*)symaddr(g_kkl);
  bf* p_w2Th = (bf*)symaddr(g_w2Th); bf* p_w2Tl = (bf*)symaddr(g_w2Tl);
  bf* p_w3Th = (bf*)symaddr(g_w3Th); bf* p_w3Tl = (bf*)symaddr(g_w3Tl);
  bf* p_ewTh = (bf*)symaddr(g_ewTh); bf* p_ewTl = (bf*)symaddr(g_ewTl);
  bf* p_aqkvTh = (bf*)symaddr(g_aqkvTh); bf* p_aqkvTl = (bf*)symaddr(g_aqkvTl);
  bf* p_awoTh  = (bf*)symaddr(g_awoTh);  bf* p_awoTl  = (bf*)symaddr(g_awoTl);
  bf* p_fkrTh  = (bf*)symaddr(g_fkrTh);  bf* p_fkrTl  = (bf*)symaddr(g_fkrTl);
  bf* p_fwvTh  = (bf*)symaddr(g_fwvTh);  bf* p_fwvTl  = (bf*)symaddr(g_fwvTl);

  // launches 1-6 (launch 6 = conv3 GEMM profiled by ncu -s 5 -c 1)
  prep_conv_k<<<(C2*K2C + C3*K3C + 255)/256, 256>>>(conv2_w, conv3_w);
  conv1_k<<<(BATCH*H1*W1*C1)/256, 256>>>(x, conv1_w, conv1_b);
  im2col2_k<<<(MCONV*(K2C/4))/256, 256>>>();
  gemm<1,0,1>(MCONV, C2, K2C, p_col2h, p_col2l, p_w2Th, p_w2Tl, conv2_b,
              nullptr, p_c2h, p_c2l, nullptr);
  im2col3_k<<<(MCONV*(K3C/4))/256, 256>>>();
  gemm<1,0,1>(MCONV, C3, K3C, p_col3h, p_col3l, p_w3Th, p_w3Tl, conv3_b,
              nullptr, p_c3h, p_c3l, nullptr);

  prep_big_k<<<18432, dim3(32,8)>>>(embed_w, awk, awv, awr, awo, fwr, fwk, fwv);
  reshape_k<<<MT, 256>>>();
  gemm<0,0,0>(MT, DIM, KE, p_yrh, p_yrl, p_ewTh, p_ewTl, embed_b,
              p_t0, nullptr, nullptr, nullptr);
  ln_k<<<MT, 128>>>(p_t0, eln_g, eln_b, p_h);

  // ---- RWKV blocks ----
  for(int i = 0; i < NB_; i++){
    long w2 = (long)i*DIM*DIM;
    long wh = (long)i*DIM*HID;
    long qb = (long)i*3*DIM*DIM;
    long fb = (long)i*(HID+DIM)*DIM;
    // time mixing
    ln_k<<<MT, 128>>>(p_h, lag + i*DIM, lab + i*DIM, p_xn);
    mix3_k<<<HTOK/512, 256>>>(p_xn, amk + i*DIM, amv + i*DIM, amr + i*DIM);
    gemm<0,0,0>(MT, DIM, DIM, p_xkh, p_xkl, p_aqkvTh + qb, p_aqkvTl + qb, nullptr,
                p_k, nullptr, nullptr, nullptr);
    gemm<0,0,0>(MT, DIM, DIM, p_xvh, p_xvl, p_aqkvTh + qb + (long)DIM*DIM,
                p_aqkvTl + qb + (long)DIM*DIM, nullptr,
                p_v, nullptr, nullptr, nullptr);
    gemm<2,0,0>(MT, DIM, DIM, p_xrh, p_xrl, p_aqkvTh + qb + 2L*DIM*DIM,
                p_aqkvTl + qb + 2L*DIM*DIM, nullptr,
                p_r, nullptr, nullptr, nullptr);
    wkv_k<<<(BATCH*DIM)/32, 32>>>(p_k, p_v, p_r, dec + i*DIM, fir + i*DIM);
    gemm<0,1,0>(MT, DIM, DIM, p_rwh, p_rwl, p_awoTh + w2, p_awoTl + w2, nullptr,
                p_h, nullptr, nullptr, nullptr);
    // channel mixing
    ln_k<<<MT, 128>>>(p_h, lfg + i*DIM, lfb + i*DIM, p_xn);
    mix2_k<<<HTOK/512, 256>>>(p_xn, fmk + i*DIM, fmr + i*DIM);
    gemm<3,0,1>(MT, HID, DIM, p_xkh, p_xkl, p_fkrTh + fb, p_fkrTl + fb, nullptr,
                nullptr, p_kkh, p_kkl, nullptr);
    gemm<2,0,0>(MT, DIM, DIM, p_xrh, p_xrl, p_fkrTh + fb + (long)HID*DIM,
                p_fkrTl + fb + (long)HID*DIM, nullptr,
                p_r, nullptr, nullptr, nullptr);
    gemm<0,2,0>(MT, DIM, HID, p_kkh, p_kkl, p_fwvTh + wh, p_fwvTl + wh, nullptr,
                p_h, nullptr, nullptr, p_r);
  }

  ln_k<<<MT, 128>>>(p_h, flg, flb, out);
  tail_k<<<1, 32>>>(x_len, out, out_size);
}